// round 1
// baseline (speedup 1.0000x reference)
#include <cuda_runtime.h>
#include <cuda_bf16.h>

// Problem constants
#define NN 32
#define CC 512
#define CM 128
#define HH 48
#define WW 48
#define HWP (HH*WW)          // 2304
#define PP 512
#define KR 9                 // 3x3

// ---------------- scratch (device globals; no allocation allowed) ----------
__device__ float g_mean[NN*CC];            // [n][c]
__device__ float g_xm[NN*CC*KR];           // [n][c][r]
__device__ float g_gk1[NN*CM];             // [n][o]
__device__ float g_sk[NN*CM*KR];           // [n][o][r]
__device__ float g_dynW[(size_t)NN*KR*CM*CM]; // [n][kk][o][c]
__device__ float g_f[(size_t)NN*CM*HWP];   // [n][o][hw]
__device__ float g_y[(size_t)NN*CM*HWP];   // [n][o][hw]

// ---------------- kernel 1: mean + 3x3 adaptive max pool -------------------
// one block per (n,c); 256 threads; plane = 48x48 split into 9 regions of 16x16
__global__ void pool_kernel(const float* __restrict__ x) {
    int c = blockIdx.x, n = blockIdx.y;
    const float* xp = x + ((size_t)(n*CC + c)) * HWP;
    int tid = threadIdx.x;
    int ih = tid >> 4, iw = tid & 15;

    float s = 0.f;
    float mx[KR];
#pragma unroll
    for (int r = 0; r < KR; r++) {
        int rh = (r/3)*16, rw = (r%3)*16;
        float v = xp[(rh+ih)*WW + rw + iw];
        s += v;
        mx[r] = v;
    }

    __shared__ float ssum[256];
    __shared__ float smax[KR][256];
    ssum[tid] = s;
#pragma unroll
    for (int r = 0; r < KR; r++) smax[r][tid] = mx[r];
    __syncthreads();
    for (int off = 128; off > 0; off >>= 1) {
        if (tid < off) {
            ssum[tid] += ssum[tid+off];
#pragma unroll
            for (int r = 0; r < KR; r++)
                smax[r][tid] = fmaxf(smax[r][tid], smax[r][tid+off]);
        }
        __syncthreads();
    }
    if (tid == 0) {
        g_mean[n*CC + c] = ssum[0] * (1.0f/(float)HWP);
#pragma unroll
        for (int r = 0; r < KR; r++) g_xm[(size_t)(n*CC + c)*KR + r] = smax[r][0];
    }
}

// ---------------- kernel 2: global+spatial branches (gk1, sk) --------------
// one block per n; 128 threads (one per output channel o)
__global__ void branch_kernel(const float* __restrict__ Wc, const float* __restrict__ bc) {
    int n = blockIdx.x;
    int o = threadIdx.x;
    __shared__ float sm[CC];
    __shared__ float sxm[CC*KR];
    for (int i = o; i < CC; i += CM) sm[i] = g_mean[n*CC + i];
    for (int i = o; i < CC*KR; i += CM) sxm[i] = g_xm[(size_t)n*CC*KR + i];
    __syncthreads();

    float acc0 = bc[o];
    float acc[KR];
#pragma unroll
    for (int r = 0; r < KR; r++) acc[r] = bc[o];
    const float* wr = Wc + (size_t)o*CC;
    for (int c = 0; c < CC; c++) {
        float w = __ldg(&wr[c]);
        acc0 += w * sm[c];
#pragma unroll
        for (int r = 0; r < KR; r++) acc[r] += w * sxm[c*KR + r];
    }
    g_gk1[n*CM + o] = fmaxf(acc0, 0.f);
#pragma unroll
    for (int r = 0; r < KR; r++) g_sk[(size_t)(n*CM + o)*KR + r] = fmaxf(acc[r], 0.f);
}

// ---------------- kernel 3: dynamic weight generation -----------------------
// blocks (r, n); 256 threads; dynW[n][r][o][c]
__global__ void dynw_kernel(const float* __restrict__ Wkk, const float* __restrict__ bkk,
                            const float* __restrict__ Wck, const float* __restrict__ bck) {
    int r = blockIdx.x, n = blockIdx.y;
    int tid = threadIdx.x;
    __shared__ float s_gk[CM], s_sk[CM];
    if (tid < CM) {
        float gk1 = g_gk1[n*CM + tid];
        s_gk[tid] = gk1 * Wkk[r] + bkk[r];               // g_kern[n][c][r]
        s_sk[tid] = g_sk[(size_t)(n*CM + tid)*KR + r];   // sk[n][c][r]
    }
    __syncthreads();
    float* dst = g_dynW + (size_t)(n*KR + r)*CM*CM;
    for (int idx = tid; idx < CM*CM; idx += 256) {
        int o = idx >> 7, c = idx & 127;
        float v = Wck[o*2] * s_gk[c] + Wck[o*2+1] * s_sk[c] + bck[o];
        dst[idx] = fmaxf(v, 0.f);
    }
}

// ---------------- generic tiled SGEMM: C[n] = act(A @ B[n] + bias) ----------
// A: [M][Kdim] row-major (shared across n).  B[n]: [Kdim][2304].  C[n]: [M][2304]
// BM=128, BN=64, BK=32; 256 threads, 8x4 per thread.
template<bool RELU>
__global__ void gemm_kernel(const float* __restrict__ A, const float* __restrict__ B,
                            float* __restrict__ C, const float* __restrict__ bias,
                            int Kdim, size_t BstrideN, size_t CstrideN) {
    constexpr int BM = 128, BN = 64, BK = 32;
    __shared__ float As[BK][BM+5];   // pad 133 -> conflict-free strided stores
    __shared__ float Bs[BK][BN];

    int n  = blockIdx.z;
    int m0 = blockIdx.y * BM;
    int n0 = blockIdx.x * BN;
    const float* Bp = B + (size_t)n*BstrideN + n0;
    float*       Cp = C + (size_t)n*CstrideN + n0;

    int tid = threadIdx.x;
    int nx = tid & 15;    // col group (*4)
    int my = tid >> 4;    // row group (*8)

    int a_k  = tid & 31;
    int a_r0 = tid >> 5;  // 0..7
    int b_c  = tid & 63;
    int b_k0 = tid >> 6;  // 0..3

    float acc[8][4];
#pragma unroll
    for (int i = 0; i < 8; i++)
#pragma unroll
        for (int j = 0; j < 4; j++) acc[i][j] = 0.f;

    for (int k0 = 0; k0 < Kdim; k0 += BK) {
#pragma unroll
        for (int rr = 0; rr < 16; rr++) {
            int r = a_r0 + rr*8;
            As[a_k][r] = A[(size_t)(m0 + r)*Kdim + k0 + a_k];
        }
#pragma unroll
        for (int kk = 0; kk < 8; kk++) {
            int k = b_k0 + kk*4;
            Bs[k][b_c] = Bp[(size_t)(k0 + k)*HWP + b_c];
        }
        __syncthreads();
#pragma unroll
        for (int k = 0; k < BK; k++) {
            float a[8], b[4];
#pragma unroll
            for (int i = 0; i < 8; i++) a[i] = As[k][my*8 + i];
#pragma unroll
            for (int j = 0; j < 4; j++) b[j] = Bs[k][nx*4 + j];
#pragma unroll
            for (int i = 0; i < 8; i++)
#pragma unroll
                for (int j = 0; j < 4; j++) acc[i][j] += a[i]*b[j];
        }
        __syncthreads();
    }

#pragma unroll
    for (int i = 0; i < 8; i++) {
        int row = m0 + my*8 + i;
        float bv = bias[row];
#pragma unroll
        for (int j = 0; j < 4; j++) {
            float v = acc[i][j] + bv;
            if (RELU) v = fmaxf(v, 0.f);
            Cp[(size_t)row*HWP + nx*4 + j] = v;
        }
    }
}

// ---------------- kernel 5: per-sample dynamic 3x3 conv ---------------------
// y[n,o,h,w] = sum_c sum_kk dynW[n,kk,o,c] * f[n,c,h+kh-1,w+kw-1] + b_ad[o]
// block = (h, n); 256 threads compute the full [128 o][48 w] row tile.
__global__ void conv_kernel(const float* __restrict__ b_ad) {
    constexpr int BK = 16;
    __shared__ float As[BK][CM+5];   // [c][o]
    __shared__ float Bs[BK][WW];     // [c][w]

    int h = blockIdx.x, n = blockIdx.y;
    int tid = threadIdx.x;
    int wx = tid & 15;   // w group (*3)
    int oy = tid >> 4;   // o group (*8)

    int cA  = tid & 15;
    int oA0 = tid >> 4;

    float acc[8][3];
#pragma unroll
    for (int i = 0; i < 8; i++)
#pragma unroll
        for (int j = 0; j < 3; j++) acc[i][j] = 0.f;

    const float* fbase = g_f + (size_t)n*CM*HWP;

    for (int kk = 0; kk < KR; kk++) {
        int kh = kk/3 - 1, kw = kk%3 - 1;
        int hr = h + kh;
        bool rowok = (hr >= 0) && (hr < HH);
        const float* dwp = g_dynW + (size_t)(n*KR + kk)*CM*CM;

        for (int c0 = 0; c0 < CM; c0 += BK) {
#pragma unroll
            for (int p = 0; p < 8; p++) {
                int o = oA0 + p*16;
                As[cA][o] = dwp[(size_t)o*CM + c0 + cA];
            }
#pragma unroll
            for (int p = 0; p < 3; p++) {
                int idx = tid + p*256;     // 0..767
                int c = idx / WW, w = idx % WW;
                int wc = w + kw;
                float v = 0.f;
                if (rowok && wc >= 0 && wc < WW)
                    v = fbase[(size_t)(c0 + c)*HWP + hr*WW + wc];
                Bs[c][w] = v;
            }
            __syncthreads();
#pragma unroll
            for (int k = 0; k < BK; k++) {
                float a[8], b[3];
#pragma unroll
                for (int i = 0; i < 8; i++) a[i] = As[k][oy*8 + i];
#pragma unroll
                for (int j = 0; j < 3; j++) b[j] = Bs[k][wx*3 + j];
#pragma unroll
                for (int i = 0; i < 8; i++)
#pragma unroll
                    for (int j = 0; j < 3; j++) acc[i][j] += a[i]*b[j];
            }
            __syncthreads();
        }
    }

    float* yp = g_y + (size_t)n*CM*HWP + h*WW;
#pragma unroll
    for (int i = 0; i < 8; i++) {
        int o = oy*8 + i;
        float bv = b_ad[o];
#pragma unroll
        for (int j = 0; j < 3; j++)
            yp[(size_t)o*HWP + wx*3 + j] = acc[i][j] + bv;
    }
}

// ---------------- launch -----------------------------------------------------
extern "C" void kernel_launch(void* const* d_in, const int* in_sizes, int n_in,
                              void* d_out, int out_size) {
    const float* x    = (const float*)d_in[0];
    const float* Wc   = (const float*)d_in[1];
    const float* bc   = (const float*)d_in[2];
    const float* Wkk  = (const float*)d_in[3];
    const float* bkk  = (const float*)d_in[4];
    const float* Wck  = (const float*)d_in[5];
    const float* bck  = (const float*)d_in[6];
    const float* b_ad = (const float*)d_in[7];
    const float* Wf   = (const float*)d_in[8];
    const float* bf   = (const float*)d_in[9];
    float* out = (float*)d_out;

    // device-global symbol addresses are used directly inside kernels
    float* df; float* dy;
    // resolve for gemm params (symbol address lookup, no allocation)
    cudaGetSymbolAddress((void**)&df, g_f);
    cudaGetSymbolAddress((void**)&dy, g_y);

    // 1) mean + 3x3 max pool of x
    pool_kernel<<<dim3(CC, NN), 256>>>(x);

    // 2) gk1 + sk
    branch_kernel<<<NN, CM>>>(Wc, bc);

    // 3) dynW
    dynw_kernel<<<dim3(KR, NN), 256>>>(Wkk, bkk, Wck, bck);

    // 4) f = relu(Wc @ x + bc): M=128, K=512
    gemm_kernel<true><<<dim3(HWP/64, 1, NN), 256>>>(
        Wc, x, df, bc, CC, (size_t)CC*HWP, (size_t)CM*HWP);

    // 5) y = dynconv(f, dynW) + b_ad
    conv_kernel<<<dim3(HH, NN), 256>>>(b_ad);

    // 6) out = Wf @ y + bf: M=512, K=128
    gemm_kernel<false><<<dim3(HWP/64, PP/128, NN), 256>>>(
        Wf, dy, out, bf, CM, (size_t)CM*HWP, (size_t)PP*HWP);
}

// round 2
// speedup vs baseline: 1.2136x; 1.2136x over previous
#include <cuda_runtime.h>
#include <cuda_bf16.h>

// Problem constants
#define NN 32
#define CC 512
#define CM 128
#define HH 48
#define WW 48
#define HWP (HH*WW)          // 2304
#define PP 512
#define KR 9                 // 3x3

typedef unsigned long long u64;

// ---------------- f32x2 packed-math helpers --------------------------------
__device__ __forceinline__ u64 pack2(float lo, float hi) {
    u64 r; asm("mov.b64 %0,{%1,%2};" : "=l"(r) : "f"(lo), "f"(hi)); return r;
}
__device__ __forceinline__ void fma2(u64& d, u64 a, u64 b) {
    asm("fma.rn.f32x2 %0,%1,%2,%0;" : "+l"(d) : "l"(a), "l"(b));
}
__device__ __forceinline__ float2 unpack2(u64 v) {
    float2 r; asm("mov.b64 {%0,%1},%2;" : "=f"(r.x), "=f"(r.y) : "l"(v)); return r;
}

// ---------------- scratch (device globals; no allocation allowed) ----------
__device__ float g_mean[NN*CC];
__device__ float g_xm[NN*CC*KR];
__device__ float g_gk1[NN*CM];
__device__ float g_sk[NN*CM*KR];
__device__ __align__(16) float g_dynW[(size_t)NN*KR*CM*CM]; // [n][kk][o][c]
__device__ __align__(16) float g_f[(size_t)NN*CM*HWP];      // [n][o][hw]
__device__ __align__(16) float g_y[(size_t)NN*CM*HWP];      // [n][o][hw]

// ---------------- kernel 1: mean + 3x3 adaptive max pool -------------------
__global__ void pool_kernel(const float* __restrict__ x) {
    int c = blockIdx.x, n = blockIdx.y;
    const float* xp = x + ((size_t)(n*CC + c)) * HWP;
    int tid = threadIdx.x;
    int ih = tid >> 4, iw = tid & 15;

    float s = 0.f;
    float mx[KR];
#pragma unroll
    for (int r = 0; r < KR; r++) {
        int rh = (r/3)*16, rw = (r%3)*16;
        float v = xp[(rh+ih)*WW + rw + iw];
        s += v;
        mx[r] = v;
    }

    __shared__ float ssum[256];
    __shared__ float smax[KR][256];
    ssum[tid] = s;
#pragma unroll
    for (int r = 0; r < KR; r++) smax[r][tid] = mx[r];
    __syncthreads();
    for (int off = 128; off > 0; off >>= 1) {
        if (tid < off) {
            ssum[tid] += ssum[tid+off];
#pragma unroll
            for (int r = 0; r < KR; r++)
                smax[r][tid] = fmaxf(smax[r][tid], smax[r][tid+off]);
        }
        __syncthreads();
    }
    if (tid == 0) {
        g_mean[n*CC + c] = ssum[0] * (1.0f/(float)HWP);
#pragma unroll
        for (int r = 0; r < KR; r++) g_xm[(size_t)(n*CC + c)*KR + r] = smax[r][0];
    }
}

// ---------------- kernel 2: global+spatial branches (gk1, sk) --------------
__global__ void branch_kernel(const float* __restrict__ Wc, const float* __restrict__ bc) {
    int n = blockIdx.x;
    int o = threadIdx.x;
    __shared__ float sm[CC];
    __shared__ float sxm[CC*KR];
    for (int i = o; i < CC; i += CM) sm[i] = g_mean[n*CC + i];
    for (int i = o; i < CC*KR; i += CM) sxm[i] = g_xm[(size_t)n*CC*KR + i];
    __syncthreads();

    float acc0 = bc[o];
    float acc[KR];
#pragma unroll
    for (int r = 0; r < KR; r++) acc[r] = bc[o];
    const float* wr = Wc + (size_t)o*CC;
    for (int c = 0; c < CC; c++) {
        float w = __ldg(&wr[c]);
        acc0 += w * sm[c];
#pragma unroll
        for (int r = 0; r < KR; r++) acc[r] += w * sxm[c*KR + r];
    }
    g_gk1[n*CM + o] = fmaxf(acc0, 0.f);
#pragma unroll
    for (int r = 0; r < KR; r++) g_sk[(size_t)(n*CM + o)*KR + r] = fmaxf(acc[r], 0.f);
}

// ---------------- kernel 3: dynamic weight generation -----------------------
__global__ void dynw_kernel(const float* __restrict__ Wkk, const float* __restrict__ bkk,
                            const float* __restrict__ Wck, const float* __restrict__ bck) {
    int r = blockIdx.x, n = blockIdx.y;
    int tid = threadIdx.x;
    __shared__ float s_gk[CM], s_sk[CM];
    if (tid < CM) {
        float gk1 = g_gk1[n*CM + tid];
        s_gk[tid] = gk1 * Wkk[r] + bkk[r];
        s_sk[tid] = g_sk[(size_t)(n*CM + tid)*KR + r];
    }
    __syncthreads();
    float* dst = g_dynW + (size_t)(n*KR + r)*CM*CM;
    for (int idx = tid; idx < CM*CM; idx += 256) {
        int o = idx >> 7, c = idx & 127;
        float v = Wck[o*2] * s_gk[c] + Wck[o*2+1] * s_sk[c] + bck[o];
        dst[idx] = fmaxf(v, 0.f);
    }
}

// ---------------- shared 8x8 f32x2 micro-kernel ------------------------------
// acc[i][j] (i = 8 rows, j = 4 col-pairs); pa: As row base (stride SA), pb: Bs.
#define MICRO_K_STEP(pa, pb, k, SA, BN)                                        \
    {                                                                          \
        float4 a0 = *(const float4*)((pa) + (k)*(SA) + my*8);                  \
        float4 a1 = *(const float4*)((pa) + (k)*(SA) + my*8 + 4);              \
        const u64* bq = (const u64*)((pb) + (k)*(BN) + nx*8);                  \
        u64 b0 = bq[0], b1 = bq[1], b2 = bq[2], b3 = bq[3];                    \
        float av[8] = {a0.x,a0.y,a0.z,a0.w,a1.x,a1.y,a1.z,a1.w};               \
        _Pragma("unroll")                                                      \
        for (int i = 0; i < 8; i++) {                                          \
            u64 ad = pack2(av[i], av[i]);                                      \
            fma2(acc[i][0], ad, b0);                                           \
            fma2(acc[i][1], ad, b1);                                           \
            fma2(acc[i][2], ad, b2);                                           \
            fma2(acc[i][3], ad, b3);                                           \
        }                                                                      \
    }

// ---------------- tiled SGEMM with f32x2: C[n] = act(A @ B[n] + bias) -------
// A: [M][Kdim] row-major (shared across n). B[n]: [Kdim][2304]. C[n]: [M][2304]
template<bool RELU>
__global__ void __launch_bounds__(256, 2) gemm_f2_kernel(
    const float* __restrict__ A, const float* __restrict__ B,
    float* __restrict__ C, const float* __restrict__ bias,
    int Kdim, size_t BstrideN, size_t CstrideN)
{
    constexpr int BM = 128, BN = 128, BK = 16, SA = 132;
    __shared__ __align__(16) float As[2][BK*SA];
    __shared__ __align__(16) float Bs[2][BK*BN];

    const int n  = blockIdx.z;
    const int m0 = blockIdx.y * BM;
    const int n0 = blockIdx.x * BN;
    const float* Bp = B + (size_t)n*BstrideN + n0;
    float*       Cp = C + (size_t)n*CstrideN + n0;

    const int tid = threadIdx.x;
    const int nx = tid & 15;          // col group (*8)
    const int my = tid >> 4;          // row group (*8)
    const int ak = tid & 15, ar = tid >> 4;          // A loader
    const int bk = tid >> 5, bc = (tid & 31) * 4;    // B loader

    u64 acc[8][4];
#pragma unroll
    for (int i = 0; i < 8; i++)
#pragma unroll
        for (int j = 0; j < 4; j++) acc[i][j] = 0ULL;

    const int nIter = Kdim / BK;
    float ra[8];
    float4 rb0, rb1;

    // prologue: tile 0 -> buffer 0
    {
        const float* Ap = A + (size_t)(m0 + ar)*Kdim + ak;
#pragma unroll
        for (int p = 0; p < 8; p++) ra[p] = Ap[(size_t)(p*16)*Kdim];
        rb0 = *(const float4*)(Bp + (size_t)bk*HWP + bc);
        rb1 = *(const float4*)(Bp + (size_t)(bk+8)*HWP + bc);
#pragma unroll
        for (int p = 0; p < 8; p++) As[0][ak*SA + ar + p*16] = ra[p];
        *(float4*)(&Bs[0][bk*BN + bc])     = rb0;
        *(float4*)(&Bs[0][(bk+8)*BN + bc]) = rb1;
    }
    __syncthreads();

    for (int it = 0; it < nIter; ++it) {
        const int cur = it & 1;
        if (it + 1 < nIter) {
            const int k0 = (it + 1) * BK;
            const float* Ap = A + (size_t)(m0 + ar)*Kdim + k0 + ak;
#pragma unroll
            for (int p = 0; p < 8; p++) ra[p] = Ap[(size_t)(p*16)*Kdim];
            rb0 = *(const float4*)(Bp + (size_t)(k0+bk)*HWP + bc);
            rb1 = *(const float4*)(Bp + (size_t)(k0+bk+8)*HWP + bc);
        }
        const float* pa = As[cur];
        const float* pb = Bs[cur];
#pragma unroll
        for (int k = 0; k < BK; k++) MICRO_K_STEP(pa, pb, k, SA, BN)

        if (it + 1 < nIter) {
            const int nxt = cur ^ 1;
#pragma unroll
            for (int p = 0; p < 8; p++) As[nxt][ak*SA + ar + p*16] = ra[p];
            *(float4*)(&Bs[nxt][bk*BN + bc])     = rb0;
            *(float4*)(&Bs[nxt][(bk+8)*BN + bc]) = rb1;
            __syncthreads();
        }
    }

#pragma unroll
    for (int i = 0; i < 8; i++) {
        const int row = m0 + my*8 + i;
        const float bv = __ldg(&bias[row]);
        float2 v0 = unpack2(acc[i][0]), v1 = unpack2(acc[i][1]);
        float2 v2 = unpack2(acc[i][2]), v3 = unpack2(acc[i][3]);
        float4 o0 = make_float4(v0.x+bv, v0.y+bv, v1.x+bv, v1.y+bv);
        float4 o1 = make_float4(v2.x+bv, v2.y+bv, v3.x+bv, v3.y+bv);
        if (RELU) {
            o0.x=fmaxf(o0.x,0.f); o0.y=fmaxf(o0.y,0.f); o0.z=fmaxf(o0.z,0.f); o0.w=fmaxf(o0.w,0.f);
            o1.x=fmaxf(o1.x,0.f); o1.y=fmaxf(o1.y,0.f); o1.z=fmaxf(o1.z,0.f); o1.w=fmaxf(o1.w,0.f);
        }
        *(float4*)(Cp + (size_t)row*HWP + nx*8)     = o0;
        *(float4*)(Cp + (size_t)row*HWP + nx*8 + 4) = o1;
    }
}

// ---------------- dynamic 3x3 conv as implicit GEMM (f32x2) -----------------
// y[n,o,hw] = sum_kk sum_c dynW[n,kk,o,c] * f[n,c,shift_kk(hw)] + b_ad[o]
// block = (hw_tile, n): output tile [128 o][128 hw]; K-loop = 9 kk x 8 c-tiles.
__global__ void __launch_bounds__(256, 2) conv_f2_kernel(const float* __restrict__ b_ad)
{
    constexpr int BN = 128, BK = 16, SA = 132;
    __shared__ __align__(16) float As[2][BK*SA];
    __shared__ __align__(16) float Bs[2][BK*BN];

    const int n   = blockIdx.y;
    const int hw0 = blockIdx.x * BN;
    const int tid = threadIdx.x;
    const int nx = tid & 15, my = tid >> 4;
    const int ak = tid & 15, ao = tid >> 4;     // A loader (dynW)
    const int hwl = tid & 127;                  // B loader: fixed hw column
    const int cb  = tid >> 7;                   // B loader: c = cb + 2j
    const int hq  = (hw0 + hwl) / WW;
    const int wq  = (hw0 + hwl) - hq * WW;

    const float* fbase  = g_f    + (size_t)n*CM*HWP;
    const float* dwbase = g_dynW + (size_t)n*KR*CM*CM;

    u64 acc[8][4];
#pragma unroll
    for (int i = 0; i < 8; i++)
#pragma unroll
        for (int j = 0; j < 4; j++) acc[i][j] = 0ULL;

    const int nIter = KR * (CM / BK);   // 72
    float ra[8], rb[8];

    // tile loaders (iteration -> regs)
    auto loadTiles = [&](int it) {
        const int kk = it >> 3;
        const int c0 = (it & 7) << 4;
        const float* dwp = dwbase + (size_t)kk*CM*CM + c0 + ak;
#pragma unroll
        for (int p = 0; p < 8; p++) ra[p] = dwp[(size_t)(ao + p*16)*CM];

        const int kh = kk/3 - 1, kw = kk - (kk/3)*3 - 1;
        const int hr = hq + kh, wc = wq + kw;
        const bool ok = (hr >= 0) && (hr < HH) && (wc >= 0) && (wc < WW);
        const float* fp = fbase + (size_t)(c0 + cb)*HWP + hr*WW + wc;
#pragma unroll
        for (int j = 0; j < 8; j++)
            rb[j] = ok ? fp[(size_t)(2*j)*HWP] : 0.f;
    };
    auto storeTiles = [&](int buf) {
#pragma unroll
        for (int p = 0; p < 8; p++) As[buf][ak*SA + ao + p*16] = ra[p];
#pragma unroll
        for (int j = 0; j < 8; j++) Bs[buf][(cb + 2*j)*BN + hwl] = rb[j];
    };

    loadTiles(0);
    storeTiles(0);
    __syncthreads();

    for (int it = 0; it < nIter; ++it) {
        const int cur = it & 1;
        if (it + 1 < nIter) loadTiles(it + 1);

        const float* pa = As[cur];
        const float* pb = Bs[cur];
#pragma unroll
        for (int k = 0; k < BK; k++) MICRO_K_STEP(pa, pb, k, SA, BN)

        if (it + 1 < nIter) {
            storeTiles(cur ^ 1);
            __syncthreads();
        }
    }

    float* yp = g_y + (size_t)n*CM*HWP + hw0;
#pragma unroll
    for (int i = 0; i < 8; i++) {
        const int o = my*8 + i;
        const float bv = __ldg(&b_ad[o]);
        float2 v0 = unpack2(acc[i][0]), v1 = unpack2(acc[i][1]);
        float2 v2 = unpack2(acc[i][2]), v3 = unpack2(acc[i][3]);
        float4 o0 = make_float4(v0.x+bv, v0.y+bv, v1.x+bv, v1.y+bv);
        float4 o1 = make_float4(v2.x+bv, v2.y+bv, v3.x+bv, v3.y+bv);
        *(float4*)(yp + (size_t)o*HWP + nx*8)     = o0;
        *(float4*)(yp + (size_t)o*HWP + nx*8 + 4) = o1;
    }
}

// ---------------- launch -----------------------------------------------------
extern "C" void kernel_launch(void* const* d_in, const int* in_sizes, int n_in,
                              void* d_out, int out_size) {
    const float* x    = (const float*)d_in[0];
    const float* Wc   = (const float*)d_in[1];
    const float* bc   = (const float*)d_in[2];
    const float* Wkk  = (const float*)d_in[3];
    const float* bkk  = (const float*)d_in[4];
    const float* Wck  = (const float*)d_in[5];
    const float* bck  = (const float*)d_in[6];
    const float* b_ad = (const float*)d_in[7];
    const float* Wf   = (const float*)d_in[8];
    const float* bf   = (const float*)d_in[9];
    float* out = (float*)d_out;

    float* df; float* dy;
    cudaGetSymbolAddress((void**)&df, g_f);
    cudaGetSymbolAddress((void**)&dy, g_y);

    // 1) mean + 3x3 max pool of x
    pool_kernel<<<dim3(CC, NN), 256>>>(x);

    // 2) gk1 + sk
    branch_kernel<<<NN, CM>>>(Wc, bc);

    // 3) dynW
    dynw_kernel<<<dim3(KR, NN), 256>>>(Wkk, bkk, Wck, bck);

    // 4) f = relu(Wc @ x + bc): M=128, K=512
    gemm_f2_kernel<true><<<dim3(HWP/128, 1, NN), 256>>>(
        Wc, x, df, bc, CC, (size_t)CC*HWP, (size_t)CM*HWP);

    // 5) y = dynconv(f, dynW) + b_ad
    conv_f2_kernel<<<dim3(HWP/128, NN), 256>>>(b_ad);

    // 6) out = Wf @ y + bf: M=512, K=128
    gemm_f2_kernel<false><<<dim3(HWP/128, PP/128, NN), 256>>>(
        Wf, dy, out, bf, CM, (size_t)CM*HWP, (size_t)PP*HWP);
}

// round 5
// speedup vs baseline: 1.5426x; 1.2711x over previous
#include <cuda_runtime.h>
#include <cuda_bf16.h>
#include <cstdint>

// Problem constants
#define NN 32
#define CC 512
#define CM 128
#define HH 48
#define WW 48
#define HWP 2304
#define PP 512
#define KR 9

// ---------------- scratch (device globals; no allocation allowed) ----------
__device__ float g_mean[NN*CC];
__device__ float g_xm[NN*CC*KR];
__device__ float g_gk1[NN*CM];
__device__ float g_sk[NN*CM*KR];
__device__ __align__(16) float g_dynW[(size_t)NN*KR*CM*CM]; // [n][kk][o][c]
__device__ __align__(16) float g_f[(size_t)NN*CM*HWP];      // [n][o][hw]
__device__ __align__(16) float g_y[(size_t)NN*CM*HWP];      // [n][o][hw]

// ---------------- PTX helpers ----------------------------------------------
__device__ __forceinline__ uint32_t su32(const void* p){
    uint32_t a; asm("{ .reg .u64 t; cvta.to.shared.u64 t, %1; cvt.u32.u64 %0, t; }"
                    : "=r"(a) : "l"(p)); return a;
}
__device__ __forceinline__ void cpa16(uint32_t d, const void* s){
    asm volatile("cp.async.cg.shared.global [%0], [%1], 16;" :: "r"(d), "l"(s));
}
__device__ __forceinline__ void cpa4z(uint32_t d, const void* s, int sz){
    asm volatile("cp.async.ca.shared.global [%0], [%1], 4, %2;" :: "r"(d), "l"(s), "r"(sz));
}
__device__ __forceinline__ void cpcommit(){ asm volatile("cp.async.commit_group;" ::: "memory"); }
template<int N> __device__ __forceinline__ void cpwait(){
    asm volatile("cp.async.wait_group %0;" :: "n"(N) : "memory");
}
// m16n8k8 tf32 MMA
__device__ __forceinline__ void mma8(float* c, const uint32_t* a, const uint32_t* b){
    asm volatile("mma.sync.aligned.m16n8k8.row.col.f32.tf32.tf32.f32 "
        "{%0,%1,%2,%3}, {%4,%5,%6,%7}, {%8,%9}, {%0,%1,%2,%3};"
        : "+f"(c[0]), "+f"(c[1]), "+f"(c[2]), "+f"(c[3])
        : "r"(a[0]), "r"(a[1]), "r"(a[2]), "r"(a[3]), "r"(b[0]), "r"(b[1]));
}
// 3xTF32 split: hi = rna_tf32(v), lo = rna_tf32(v - hi)
__device__ __forceinline__ uint32_t f2tf32(float x){
    uint32_t r; asm("cvt.rna.tf32.f32 %0, %1;" : "=r"(r) : "f"(x)); return r;
}
__device__ __forceinline__ void split2(uint32_t v, uint32_t& hi, uint32_t& lo){
    float f = __uint_as_float(v);
    hi = f2tf32(f);
    lo = f2tf32(f - __uint_as_float(hi));
}

// smem geometry (in uint32 units)
#define SA 36                    // A tile row pitch (128x32 + pad 4)
#define ABUF (128*SA)            // 4608 u32
#define BBUF (32*128)            // 4096 u32
#define SMEM_BYTES ((2*ABUF + 2*BBUF)*4)   // 69632

// ---------------- kernel 1: mean + 3x3 adaptive max pool (coalesced) -------
__global__ void pool_kernel(const float* __restrict__ x) {
    const int g = threadIdx.x >> 4, l = threadIdx.x & 15;
    const int c = blockIdx.x*16 + g, n = blockIdx.y;
    const float4* xp = (const float4*)(x + (size_t)(n*CC + c)*HWP);

    float s = 0.f;
    float mx[KR];
#pragma unroll
    for (int r = 0; r < KR; r++) {
        const int hb = r/3, wb = r - (r/3)*3;
        float mr = -3.402823466e38f;
#pragma unroll
        for (int j = 0; j < 4; j++) {
            int idx = j*16 + l;
            int row = idx >> 2, w4 = idx & 3;
            float4 v = xp[(hb*16 + row)*12 + wb*4 + w4];
            s += v.x + v.y + v.z + v.w;
            mr = fmaxf(mr, fmaxf(fmaxf(v.x, v.y), fmaxf(v.z, v.w)));
        }
        mx[r] = mr;
    }
#pragma unroll
    for (int o = 8; o > 0; o >>= 1) {
        s += __shfl_down_sync(0xffffffffu, s, o, 16);
#pragma unroll
        for (int r = 0; r < KR; r++)
            mx[r] = fmaxf(mx[r], __shfl_down_sync(0xffffffffu, mx[r], o, 16));
    }
    if (l == 0) {
        g_mean[n*CC + c] = s * (1.0f/(float)HWP);
#pragma unroll
        for (int r = 0; r < KR; r++) g_xm[(size_t)(n*CC + c)*KR + r] = mx[r];
    }
}

// ---------------- kernel 2: global+spatial branches (gk1, sk) --------------
__global__ void branch_kernel(const float* __restrict__ Wc, const float* __restrict__ bc) {
    int n = blockIdx.x;
    int o = threadIdx.x;
    __shared__ float sm[CC];
    __shared__ float sxm[CC*KR];
    for (int i = o; i < CC; i += CM) sm[i] = g_mean[n*CC + i];
    for (int i = o; i < CC*KR; i += CM) sxm[i] = g_xm[(size_t)n*CC*KR + i];
    __syncthreads();

    float acc0 = bc[o];
    float acc[KR];
#pragma unroll
    for (int r = 0; r < KR; r++) acc[r] = bc[o];
    const float* wr = Wc + (size_t)o*CC;
    for (int c = 0; c < CC; c++) {
        float w = __ldg(&wr[c]);
        acc0 += w * sm[c];
#pragma unroll
        for (int r = 0; r < KR; r++) acc[r] += w * sxm[c*KR + r];
    }
    g_gk1[n*CM + o] = fmaxf(acc0, 0.f);
#pragma unroll
    for (int r = 0; r < KR; r++) g_sk[(size_t)(n*CM + o)*KR + r] = fmaxf(acc[r], 0.f);
}

// ---------------- kernel 3: dynamic weight generation -----------------------
__global__ void dynw_kernel(const float* __restrict__ Wkk, const float* __restrict__ bkk,
                            const float* __restrict__ Wck, const float* __restrict__ bck) {
    int r = blockIdx.x, n = blockIdx.y;
    int tid = threadIdx.x;
    __shared__ float s_gk[CM], s_sk[CM];
    if (tid < CM) {
        float gk1 = g_gk1[n*CM + tid];
        s_gk[tid] = gk1 * Wkk[r] + bkk[r];
        s_sk[tid] = g_sk[(size_t)(n*CM + tid)*KR + r];
    }
    __syncthreads();
    float* dst = g_dynW + (size_t)(n*KR + r)*CM*CM;
    for (int idx = tid; idx < CM*CM; idx += 256) {
        int o = idx >> 7, c = idx & 127;
        float v = Wck[o*2] * s_gk[c] + Wck[o*2+1] * s_sk[c] + bck[o];
        dst[idx] = fmaxf(v, 0.f);
    }
}

// ---------------- shared mma.sync compute step (3xTF32) ---------------------
// warp tile 32(m) x 64(n): 2 m-tiles x 8 n-tiles of m16n8k8, BK=32 (4 k8 steps)
__device__ __forceinline__ void mma_compute(
    const uint32_t* pa, const uint32_t* pb, float acc[2][8][4],
    int wm, int wn, int lane)
{
    const int lq = lane >> 2, lr = lane & 3;
#pragma unroll
    for (int k8 = 0; k8 < 4; k8++) {
        uint32_t ah[2][4], al[2][4];
        const int c0 = k8*8 + lr;
        const int r0 = wm*32 + lq;
#pragma unroll
        for (int mt = 0; mt < 2; mt++) {
            const uint32_t* q = pa + (r0 + mt*16)*SA + c0;
            uint32_t raw0 = q[0], raw1 = q[8*SA], raw2 = q[4], raw3 = q[8*SA + 4];
            split2(raw0, ah[mt][0], al[mt][0]);
            split2(raw1, ah[mt][1], al[mt][1]);
            split2(raw2, ah[mt][2], al[mt][2]);
            split2(raw3, ah[mt][3], al[mt][3]);
        }
        const int kb  = k8*8 + lr;
        const int swz = (kb & 3) << 3;
        const int nb  = wn*64 + lq;
#pragma unroll
        for (int nt = 0; nt < 8; nt++) {
            const int col = (nb + nt*8) ^ swz;
            uint32_t b0 = pb[kb*128 + col];
            uint32_t b1 = pb[(kb+4)*128 + col];
            uint32_t bh[2], bl[2];
            split2(b0, bh[0], bl[0]);
            split2(b1, bh[1], bl[1]);
#pragma unroll
            for (int mt = 0; mt < 2; mt++) {
                mma8(acc[mt][nt], ah[mt], bh);   // hi*hi
                mma8(acc[mt][nt], al[mt], bh);   // lo*hi
                mma8(acc[mt][nt], ah[mt], bl);   // hi*lo
            }
        }
    }
}

// ---------------- tf32x3 mma GEMM: C[n] = act(A @ B[n] + bias) --------------
template<bool RELU>
__global__ void __launch_bounds__(256, 2) gemm_mma(
    const float* __restrict__ A, const float* __restrict__ B,
    float* __restrict__ C, const float* __restrict__ bias,
    int Kd, size_t BstrN, size_t CstrN)
{
    extern __shared__ uint32_t sm[];
    uint32_t* Asm = sm;
    uint32_t* Bsm = sm + 2*ABUF;
    const uint32_t sAs = su32(Asm), sBs = su32(Bsm);

    const int tid = threadIdx.x, lane = tid & 31, wid = tid >> 5;
    const int wm = wid & 3, wn = wid >> 2;
    const int n0 = blockIdx.x * 128;
    const int m0 = blockIdx.y * 128;
    const int n  = blockIdx.z;
    const float* Bp = B + (size_t)n*BstrN + n0;
    float*       Cp = C + (size_t)n*CstrN;

    const int am = tid >> 3;            // 0..31 (+32p)
    const int ak = (tid & 7) * 4;       // 0..28
    const int bn4 = (tid & 31) * 4;     // 0..124
    const int bk  = tid >> 5;           // 0..7 (+8q)

    float acc[2][8][4];
#pragma unroll
    for (int i = 0; i < 2; i++)
#pragma unroll
        for (int j = 0; j < 8; j++)
#pragma unroll
            for (int t = 0; t < 4; t++) acc[i][j][t] = 0.f;

    auto issue = [&](int it) {
        const int buf = it & 1;
        const int k0 = it * 32;
        const float* p = A + (size_t)(m0 + am)*Kd + k0 + ak;
        const uint32_t da = sAs + (uint32_t)(buf*ABUF + am*SA + ak)*4;
#pragma unroll
        for (int i = 0; i < 4; i++)
            cpa16(da + i*32*SA*4, p + (size_t)i*32*Kd);
        const uint32_t db = sBs + (uint32_t)(buf*BBUF)*4;
#pragma unroll
        for (int q = 0; q < 4; q++) {
            const int k = bk + q*8;
            cpa16(db + (uint32_t)(k*128 + (bn4 ^ ((k & 3) << 3)))*4,
                  Bp + (size_t)(k0 + k)*HWP + bn4);
        }
        cpcommit();
    };

    const int nIter = Kd / 32;
    issue(0);
    for (int it = 0; it < nIter; ++it) {
        if (it + 1 < nIter) { issue(it + 1); cpwait<1>(); }
        else cpwait<0>();
        __syncthreads();
        const int buf = it & 1;
        mma_compute(Asm + buf*ABUF, Bsm + buf*BBUF, acc, wm, wn, lane);
        __syncthreads();
    }

    const int lq = lane >> 2, lr = lane & 3;
#pragma unroll
    for (int mt = 0; mt < 2; mt++) {
        const int r0 = m0 + wm*32 + mt*16 + lq;
        const float bv0 = __ldg(&bias[r0]);
        const float bv1 = __ldg(&bias[r0 + 8]);
#pragma unroll
        for (int nt = 0; nt < 8; nt++) {
            const int cb = n0 + wn*64 + nt*8 + 2*lr;
            float2 v0 = make_float2(acc[mt][nt][0] + bv0, acc[mt][nt][1] + bv0);
            float2 v1 = make_float2(acc[mt][nt][2] + bv1, acc[mt][nt][3] + bv1);
            if (RELU) {
                v0.x = fmaxf(v0.x, 0.f); v0.y = fmaxf(v0.y, 0.f);
                v1.x = fmaxf(v1.x, 0.f); v1.y = fmaxf(v1.y, 0.f);
            }
            *(float2*)(Cp + (size_t)r0*HWP + cb)       = v0;
            *(float2*)(Cp + (size_t)(r0 + 8)*HWP + cb) = v1;
        }
    }
}

// ---------------- dynamic 3x3 conv as implicit GEMM (tf32x3 mma) ------------
__global__ void __launch_bounds__(256, 2) conv_mma(const float* __restrict__ b_ad)
{
    extern __shared__ uint32_t sm[];
    uint32_t* Asm = sm;
    uint32_t* Bsm = sm + 2*ABUF;
    const uint32_t sAs = su32(Asm), sBs = su32(Bsm);

    const int tid = threadIdx.x, lane = tid & 31, wid = tid >> 5;
    const int wm = wid & 3, wn = wid >> 2;
    const int hw0 = blockIdx.x * 128;
    const int n   = blockIdx.y;
    const float* fb  = g_f    + (size_t)n*CM*HWP;
    const float* dwb = g_dynW + (size_t)n*KR*CM*CM;

    const int am = tid >> 3;
    const int ak = (tid & 7) * 4;
    const int hwl = tid & 127;
    const int ch  = tid >> 7;
    const int hq = (hw0 + hwl) / WW;
    const int wq = (hw0 + hwl) - hq * WW;

    float acc[2][8][4];
#pragma unroll
    for (int i = 0; i < 2; i++)
#pragma unroll
        for (int j = 0; j < 8; j++)
#pragma unroll
            for (int t = 0; t < 4; t++) acc[i][j][t] = 0.f;

    auto issue = [&](int it) {
        const int buf = it & 1;
        const int kk = it >> 2, c0 = (it & 3) * 32;
        const float* p = dwb + (size_t)kk*CM*CM + (size_t)am*CM + c0 + ak;
        const uint32_t da = sAs + (uint32_t)(buf*ABUF + am*SA + ak)*4;
#pragma unroll
        for (int i = 0; i < 4; i++)
            cpa16(da + i*32*SA*4, p + (size_t)i*32*CM);
        const int kh = kk/3 - 1, kw = kk - (kk/3)*3 - 1;
        const int hr = hq + kh, wc = wq + kw;
        const bool ok = (hr >= 0) && (hr < HH) && (wc >= 0) && (wc < WW);
        const float* fp = ok ? (fb + hr*WW + wc) : fb;
        const int sz = ok ? 4 : 0;
        const uint32_t db = sBs + (uint32_t)(buf*BBUF)*4;
#pragma unroll
        for (int j = 0; j < 16; j++) {
            const int cc = ch*16 + j;
            cpa4z(db + (uint32_t)(cc*128 + (hwl ^ ((cc & 3) << 3)))*4,
                  fp + (size_t)(c0 + cc)*HWP, sz);
        }
        cpcommit();
    };

    const int nIter = KR * 4;   // 36
    issue(0);
    for (int it = 0; it < nIter; ++it) {
        if (it + 1 < nIter) { issue(it + 1); cpwait<1>(); }
        else cpwait<0>();
        __syncthreads();
        const int buf = it & 1;
        mma_compute(Asm + buf*ABUF, Bsm + buf*BBUF, acc, wm, wn, lane);
        __syncthreads();
    }

    const int lq = lane >> 2, lr = lane & 3;
    float* yb = g_y + (size_t)n*CM*HWP;
#pragma unroll
    for (int mt = 0; mt < 2; mt++) {
        const int o0 = wm*32 + mt*16 + lq;
        const float bv0 = __ldg(&b_ad[o0]);
        const float bv1 = __ldg(&b_ad[o0 + 8]);
#pragma unroll
        for (int nt = 0; nt < 8; nt++) {
            const int cb = hw0 + wn*64 + nt*8 + 2*lr;
            float2 v0 = make_float2(acc[mt][nt][0] + bv0, acc[mt][nt][1] + bv0);
            float2 v1 = make_float2(acc[mt][nt][2] + bv1, acc[mt][nt][3] + bv1);
            *(float2*)(yb + (size_t)o0*HWP + cb)       = v0;
            *(float2*)(yb + (size_t)(o0 + 8)*HWP + cb) = v1;
        }
    }
}

// ---------------- launch -----------------------------------------------------
extern "C" void kernel_launch(void* const* d_in, const int* in_sizes, int n_in,
                              void* d_out, int out_size) {
    const float* x    = (const float*)d_in[0];
    const float* Wc   = (const float*)d_in[1];
    const float* bc   = (const float*)d_in[2];
    const float* Wkk  = (const float*)d_in[3];
    const float* bkk  = (const float*)d_in[4];
    const float* Wck  = (const float*)d_in[5];
    const float* bck  = (const float*)d_in[6];
    const float* b_ad = (const float*)d_in[7];
    const float* Wf   = (const float*)d_in[8];
    const float* bf   = (const float*)d_in[9];
    float* out = (float*)d_out;

    float* df; float* dy;
    cudaGetSymbolAddress((void**)&df, g_f);
    cudaGetSymbolAddress((void**)&dy, g_y);

    cudaFuncSetAttribute(gemm_mma<true>,  cudaFuncAttributeMaxDynamicSharedMemorySize, SMEM_BYTES);
    cudaFuncSetAttribute(gemm_mma<false>, cudaFuncAttributeMaxDynamicSharedMemorySize, SMEM_BYTES);
    cudaFuncSetAttribute(conv_mma,        cudaFuncAttributeMaxDynamicSharedMemorySize, SMEM_BYTES);

    // 1) mean + 3x3 max pool of x
    pool_kernel<<<dim3(CC/16, NN), 256>>>(x);

    // 2) gk1 + sk
    branch_kernel<<<NN, CM>>>(Wc, bc);

    // 3) dynW
    dynw_kernel<<<dim3(KR, NN), 256>>>(Wkk, bkk, Wck, bck);

    // 4) f = relu(Wc @ x + bc): M=128, K=512  (tf32x3 mma)
    gemm_mma<true><<<dim3(HWP/128, 1, NN), 256, SMEM_BYTES>>>(
        Wc, x, df, bc, CC, (size_t)CC*HWP, (size_t)CM*HWP);

    // 5) y = dynconv(f, dynW) + b_ad  (tf32x3 mma implicit GEMM)
    conv_mma<<<dim3(HWP/128, NN), 256, SMEM_BYTES>>>(b_ad);

    // 6) out = Wf @ y + bf: M=512, K=128  (tf32x3 mma)
    gemm_mma<false><<<dim3(HWP/128, PP/128, NN), 256, SMEM_BYTES>>>(
        Wf, dy, out, bf, CM, (size_t)CM*HWP, (size_t)PP*HWP);
}

// round 6
// speedup vs baseline: 1.9072x; 1.2364x over previous
#include <cuda_runtime.h>
#include <cuda_bf16.h>
#include <cstdint>

// Problem constants
#define NN 32
#define CC 512
#define CM 128
#define HH 48
#define WW 48
#define HWP 2304
#define PP 512
#define KR 9

// ---------------- scratch (device globals; no allocation allowed) ----------
__device__ float g_mean[NN*CC];
__device__ float g_xm[NN*CC*KR];
__device__ float g_gk1[NN*CM];
__device__ float g_sk[NN*CM*KR];
__device__ __align__(16) float g_dynW[(size_t)NN*KR*CM*CM]; // [n][kk][o][c]
__device__ __align__(16) float g_f[(size_t)NN*CM*HWP];      // [n][o][hw]
__device__ __align__(16) float g_y[(size_t)NN*CM*HWP];      // [n][o][hw]

// ---------------- helpers ----------------------------------------------------
// bf16 m16n8k16 MMA
__device__ __forceinline__ void mma16(float* c, const uint32_t* a, const uint32_t* b){
    asm volatile("mma.sync.aligned.m16n8k16.row.col.f32.bf16.bf16.f32 "
        "{%0,%1,%2,%3}, {%4,%5,%6,%7}, {%8,%9}, {%0,%1,%2,%3};"
        : "+f"(c[0]), "+f"(c[1]), "+f"(c[2]), "+f"(c[3])
        : "r"(a[0]), "r"(a[1]), "r"(a[2]), "r"(a[3]), "r"(b[0]), "r"(b[1]));
}
// 2-term bf16 split: f = hi + lo (+ O(2^-17 f))
__device__ __forceinline__ void bsplit(float f, uint16_t& h, uint16_t& l){
    __nv_bfloat16 bh = __float2bfloat16(f);
    float r = f - __bfloat162float(bh);
    __nv_bfloat16 bl = __float2bfloat16(r);
    h = __bfloat16_as_ushort(bh);
    l = __bfloat16_as_ushort(bl);
}
__device__ __forceinline__ uint32_t pk(uint16_t a, uint16_t b){
    return (uint32_t)a | ((uint32_t)b << 16);
}

// smem geometry (u32 units). A: [128 rows][48 words + pad->52]; B: [48 words][128 cols]
#define AP 52
#define AWBUF (128*AP)          // 6656
#define BWBUF (48*128)          // 6144
#define BUFW  (AWBUF + BWBUF)   // 12800
#define SMEM_BYTES (2*BUFW*4)   // 102400

// ---------------- kernel 1: mean + 3x3 adaptive max pool (coalesced) -------
__global__ void pool_kernel(const float* __restrict__ x) {
    const int g = threadIdx.x >> 4, l = threadIdx.x & 15;
    const int c = blockIdx.x*16 + g, n = blockIdx.y;
    const float4* xp = (const float4*)(x + (size_t)(n*CC + c)*HWP);

    float s = 0.f;
    float mx[KR];
#pragma unroll
    for (int r = 0; r < KR; r++) {
        const int hb = r/3, wb = r - (r/3)*3;
        float mr = -3.402823466e38f;
#pragma unroll
        for (int j = 0; j < 4; j++) {
            int idx = j*16 + l;
            int row = idx >> 2, w4 = idx & 3;
            float4 v = xp[(hb*16 + row)*12 + wb*4 + w4];
            s += v.x + v.y + v.z + v.w;
            mr = fmaxf(mr, fmaxf(fmaxf(v.x, v.y), fmaxf(v.z, v.w)));
        }
        mx[r] = mr;
    }
#pragma unroll
    for (int o = 8; o > 0; o >>= 1) {
        s += __shfl_down_sync(0xffffffffu, s, o, 16);
#pragma unroll
        for (int r = 0; r < KR; r++)
            mx[r] = fmaxf(mx[r], __shfl_down_sync(0xffffffffu, mx[r], o, 16));
    }
    if (l == 0) {
        g_mean[n*CC + c] = s * (1.0f/(float)HWP);
#pragma unroll
        for (int r = 0; r < KR; r++) g_xm[(size_t)(n*CC + c)*KR + r] = mx[r];
    }
}

// ---------------- kernel 2: global+spatial branches (gk1, sk) --------------
__global__ void branch_kernel(const float* __restrict__ Wc, const float* __restrict__ bc) {
    int n = blockIdx.x;
    int o = threadIdx.x;
    __shared__ float sm[CC];
    __shared__ float sxm[CC*KR];
    for (int i = o; i < CC; i += CM) sm[i] = g_mean[n*CC + i];
    for (int i = o; i < CC*KR; i += CM) sxm[i] = g_xm[(size_t)n*CC*KR + i];
    __syncthreads();

    float acc0 = bc[o];
    float acc[KR];
#pragma unroll
    for (int r = 0; r < KR; r++) acc[r] = bc[o];
    const float* wr = Wc + (size_t)o*CC;
    for (int c = 0; c < CC; c++) {
        float w = __ldg(&wr[c]);
        acc0 += w * sm[c];
#pragma unroll
        for (int r = 0; r < KR; r++) acc[r] += w * sxm[c*KR + r];
    }
    g_gk1[n*CM + o] = fmaxf(acc0, 0.f);
#pragma unroll
    for (int r = 0; r < KR; r++) g_sk[(size_t)(n*CM + o)*KR + r] = fmaxf(acc[r], 0.f);
}

// ---------------- kernel 3: dynamic weight generation -----------------------
__global__ void dynw_kernel(const float* __restrict__ Wkk, const float* __restrict__ bkk,
                            const float* __restrict__ Wck, const float* __restrict__ bck) {
    int r = blockIdx.x, n = blockIdx.y;
    int tid = threadIdx.x;
    __shared__ float s_gk[CM], s_sk[CM];
    if (tid < CM) {
        float gk1 = g_gk1[n*CM + tid];
        s_gk[tid] = gk1 * Wkk[r] + bkk[r];
        s_sk[tid] = g_sk[(size_t)(n*CM + tid)*KR + r];
    }
    __syncthreads();
    float* dst = g_dynW + (size_t)(n*KR + r)*CM*CM;
    for (int idx = tid; idx < CM*CM; idx += 256) {
        int o = idx >> 7, c = idx & 127;
        float v = Wck[o*2] * s_gk[c] + Wck[o*2+1] * s_sk[c] + bck[o];
        dst[idx] = fmaxf(v, 0.f);
    }
}

// ---------------- bf16 triple-K smem store helpers ---------------------------
// A: 4 consecutive fp32 k (t0 even) -> 6 u32 words [h0,l0][h0,h1][l1,h1][h2,l2][h2,h3][l3,h3]
__device__ __forceinline__ void storeA4(uint32_t* dst, float4 v){
    uint16_t h0,l0,h1,l1,h2,l2,h3,l3;
    bsplit(v.x, h0, l0); bsplit(v.y, h1, l1);
    bsplit(v.z, h2, l2); bsplit(v.w, h3, l3);
    *(uint2*)(dst)     = make_uint2(pk(h0,l0), pk(h0,h1));
    *(uint2*)(dst + 2) = make_uint2(pk(l1,h1), pk(h2,l2));
    *(uint2*)(dst + 4) = make_uint2(pk(h2,h3), pk(l3,h3));
}
// B: two consecutive fp32 k rows (k even), 4 cols -> 3 swizzled uint4 stores
// words: [H0,H0][L0,H1][H1,L1] per col
__device__ __forceinline__ void storeB2x4(uint32_t* bw, int wp, int bn4,
                                          const float* r0, const float* r1){
    uint32_t w0[4], w1[4], w2[4];
#pragma unroll
    for (int j = 0; j < 4; j++) {
        uint16_t H0,L0,H1,L1;
        bsplit(r0[j], H0, L0);
        bsplit(r1[j], H1, L1);
        w0[j] = pk(H0,H0); w1[j] = pk(L0,H1); w2[j] = pk(H1,L1);
    }
    *(uint4*)(bw + (wp  )*128 + (bn4 ^ (((wp  )&3)<<3))) = make_uint4(w0[0],w0[1],w0[2],w0[3]);
    *(uint4*)(bw + (wp+1)*128 + (bn4 ^ (((wp+1)&3)<<3))) = make_uint4(w1[0],w1[1],w1[2],w1[3]);
    *(uint4*)(bw + (wp+2)*128 + (bn4 ^ (((wp+2)&3)<<3))) = make_uint4(w2[0],w2[1],w2[2],w2[3]);
}

// ---------------- shared bf16 mma compute (96 bf16 k = 6 k16 steps) ----------
__device__ __forceinline__ void mma_compute(
    const uint32_t* pa, const uint32_t* pb, float acc[2][8][4],
    int wm, int wn, int lane)
{
    const int lq = lane >> 2, lr = lane & 3;
#pragma unroll
    for (int s = 0; s < 6; s++) {
        const int w0 = s*8 + lr;
        uint32_t a[2][4];
#pragma unroll
        for (int mt = 0; mt < 2; mt++) {
            const uint32_t* q = pa + (wm*32 + mt*16 + lq)*AP + w0;
            a[mt][0] = q[0];
            a[mt][1] = q[8*AP];
            a[mt][2] = q[4];
            a[mt][3] = q[8*AP + 4];
        }
        const int xr = (w0 & 3) << 3;
        const int nb = wn*64 + lq;
#pragma unroll
        for (int nt = 0; nt < 8; nt++) {
            const int col = (nb + nt*8) ^ xr;
            uint32_t b[2];
            b[0] = pb[w0*128 + col];
            b[1] = pb[(w0+4)*128 + col];
            mma16(acc[0][nt], a[0], b);
            mma16(acc[1][nt], a[1], b);
        }
    }
}

// ---------------- bf16x3 mma GEMM: C[n] = act(A @ B[n] + bias) ---------------
template<bool RELU>
__global__ void __launch_bounds__(256, 2) gemm_mma(
    const float* __restrict__ A, const float* __restrict__ B,
    float* __restrict__ C, const float* __restrict__ bias,
    int Kd, size_t BstrN, size_t CstrN)
{
    extern __shared__ uint32_t sm[];

    const int tid = threadIdx.x, lane = tid & 31, wid = tid >> 5;
    const int wm = wid & 3, wn = wid >> 2;
    const int n0 = blockIdx.x * 128;
    const int m0 = blockIdx.y * 128;
    const int nb = blockIdx.z;
    const float* Bp = B + (size_t)nb*BstrN + n0;
    float*       Cp = C + (size_t)nb*CstrN;

    // loader coords
    const int am  = tid >> 3;           // A rows am + 32p
    const int ak4 = (tid & 7) * 4;      // A k chunk (even pair-aligned)
    const int kb2 = (tid >> 5) * 2;     // B k rows kb2+16q, +1
    const int bn4 = (tid & 31) * 4;     // B cols

    float acc[2][8][4];
#pragma unroll
    for (int i = 0; i < 2; i++)
#pragma unroll
        for (int j = 0; j < 8; j++)
#pragma unroll
            for (int t = 0; t < 4; t++) acc[i][j][t] = 0.f;

    float4 rA[4];
    float4 rB[2][2];

    auto ldg = [&](int it){
        const int k0 = it * 32;
#pragma unroll
        for (int p = 0; p < 4; p++)
            rA[p] = *(const float4*)(A + (size_t)(m0 + am + p*32)*Kd + k0 + ak4);
#pragma unroll
        for (int q = 0; q < 2; q++) {
            const int k = k0 + kb2 + q*16;
            rB[q][0] = *(const float4*)(Bp + (size_t)k*HWP + bn4);
            rB[q][1] = *(const float4*)(Bp + (size_t)(k+1)*HWP + bn4);
        }
    };
    auto sts = [&](int buf){
        uint32_t* aw = sm + buf*BUFW;
        uint32_t* bw = aw + AWBUF;
        const int w0 = (tid & 7) * 6;
#pragma unroll
        for (int p = 0; p < 4; p++)
            storeA4(aw + (am + p*32)*AP + w0, rA[p]);
#pragma unroll
        for (int q = 0; q < 2; q++)
            storeB2x4(bw, ((tid>>5) + q*8)*3, bn4, (const float*)&rB[q][0], (const float*)&rB[q][1]);
    };

    const int nIter = Kd / 32;
    ldg(0); sts(0); __syncthreads();
    for (int it = 0; it < nIter; ++it) {
        const int cur = it & 1;
        if (it + 1 < nIter) ldg(it + 1);
        mma_compute(sm + cur*BUFW, sm + cur*BUFW + AWBUF, acc, wm, wn, lane);
        if (it + 1 < nIter) { sts(cur ^ 1); __syncthreads(); }
    }

    const int lq = lane >> 2, lr = lane & 3;
#pragma unroll
    for (int mt = 0; mt < 2; mt++) {
        const int r0 = m0 + wm*32 + mt*16 + lq;
        const float bv0 = __ldg(&bias[r0]);
        const float bv1 = __ldg(&bias[r0 + 8]);
#pragma unroll
        for (int nt = 0; nt < 8; nt++) {
            const int cb = n0 + wn*64 + nt*8 + 2*lr;
            float2 v0 = make_float2(acc[mt][nt][0] + bv0, acc[mt][nt][1] + bv0);
            float2 v1 = make_float2(acc[mt][nt][2] + bv1, acc[mt][nt][3] + bv1);
            if (RELU) {
                v0.x = fmaxf(v0.x, 0.f); v0.y = fmaxf(v0.y, 0.f);
                v1.x = fmaxf(v1.x, 0.f); v1.y = fmaxf(v1.y, 0.f);
            }
            *(float2*)(Cp + (size_t)r0*HWP + cb)       = v0;
            *(float2*)(Cp + (size_t)(r0 + 8)*HWP + cb) = v1;
        }
    }
}

// ---------------- dynamic 3x3 conv as implicit GEMM (bf16x3 mma) -------------
__global__ void __launch_bounds__(256, 2) conv_mma(const float* __restrict__ b_ad)
{
    extern __shared__ uint32_t sm[];

    const int tid = threadIdx.x, lane = tid & 31, wid = tid >> 5;
    const int wm = wid & 3, wn = wid >> 2;
    const int hw0 = blockIdx.x * 128;
    const int nb  = blockIdx.y;
    const float* fb  = g_f    + (size_t)nb*CM*HWP;
    const float* dwb = g_dynW + (size_t)nb*KR*CM*CM;

    const int am  = tid >> 3;
    const int ak4 = (tid & 7) * 4;
    const int cb2 = (tid >> 5) * 2;     // channel rows cb2+16q, +1
    const int bn4 = (tid & 31) * 4;

    // per-col fixed output coords
    int oh[4], ow[4];
#pragma unroll
    for (int j = 0; j < 4; j++) {
        const int hwg = hw0 + bn4 + j;
        oh[j] = hwg / WW;
        ow[j] = hwg - oh[j]*WW;
    }

    float acc[2][8][4];
#pragma unroll
    for (int i = 0; i < 2; i++)
#pragma unroll
        for (int j = 0; j < 8; j++)
#pragma unroll
            for (int t = 0; t < 4; t++) acc[i][j][t] = 0.f;

    float4 rA[4];
    float  rB[2][2][4];

    auto ldg = [&](int it){
        const int kk = it >> 2, c0 = (it & 3) * 32;
        const float* dw = dwb + (size_t)kk*CM*CM;
#pragma unroll
        for (int p = 0; p < 4; p++)
            rA[p] = *(const float4*)(dw + (size_t)(am + p*32)*CM + c0 + ak4);
        const int kh = kk/3 - 1, kw = kk - (kk/3)*3 - 1;
        int  off[4];
        bool ok[4];
#pragma unroll
        for (int j = 0; j < 4; j++) {
            const int hr = oh[j] + kh, wc = ow[j] + kw;
            ok[j]  = (hr >= 0) && (hr < HH) && (wc >= 0) && (wc < WW);
            off[j] = ok[j] ? (hr*WW + wc) : 0;
        }
#pragma unroll
        for (int q = 0; q < 2; q++) {
            const int c = c0 + cb2 + q*16;
#pragma unroll
            for (int j = 0; j < 4; j++) {
                rB[q][0][j] = ok[j] ? __ldg(fb + (size_t)c*HWP + off[j])       : 0.f;
                rB[q][1][j] = ok[j] ? __ldg(fb + (size_t)(c+1)*HWP + off[j])   : 0.f;
            }
        }
    };
    auto sts = [&](int buf){
        uint32_t* aw = sm + buf*BUFW;
        uint32_t* bw = aw + AWBUF;
        const int w0 = (tid & 7) * 6;
#pragma unroll
        for (int p = 0; p < 4; p++)
            storeA4(aw + (am + p*32)*AP + w0, rA[p]);
#pragma unroll
        for (int q = 0; q < 2; q++)
            storeB2x4(bw, ((tid>>5) + q*8)*3, bn4, rB[q][0], rB[q][1]);
    };

    const int nIter = KR * 4;   // 36
    ldg(0); sts(0); __syncthreads();
    for (int it = 0; it < nIter; ++it) {
        const int cur = it & 1;
        if (it + 1 < nIter) ldg(it + 1);
        mma_compute(sm + cur*BUFW, sm + cur*BUFW + AWBUF, acc, wm, wn, lane);
        if (it + 1 < nIter) { sts(cur ^ 1); __syncthreads(); }
    }

    const int lq = lane >> 2, lr = lane & 3;
    float* yb = g_y + (size_t)nb*CM*HWP;
#pragma unroll
    for (int mt = 0; mt < 2; mt++) {
        const int o0 = wm*32 + mt*16 + lq;
        const float bv0 = __ldg(&b_ad[o0]);
        const float bv1 = __ldg(&b_ad[o0 + 8]);
#pragma unroll
        for (int nt = 0; nt < 8; nt++) {
            const int cb = hw0 + wn*64 + nt*8 + 2*lr;
            float2 v0 = make_float2(acc[mt][nt][0] + bv0, acc[mt][nt][1] + bv0);
            float2 v1 = make_float2(acc[mt][nt][2] + bv1, acc[mt][nt][3] + bv1);
            *(float2*)(yb + (size_t)o0*HWP + cb)       = v0;
            *(float2*)(yb + (size_t)(o0 + 8)*HWP + cb) = v1;
        }
    }
}

// ---------------- launch -----------------------------------------------------
extern "C" void kernel_launch(void* const* d_in, const int* in_sizes, int n_in,
                              void* d_out, int out_size) {
    const float* x    = (const float*)d_in[0];
    const float* Wc   = (const float*)d_in[1];
    const float* bc   = (const float*)d_in[2];
    const float* Wkk  = (const float*)d_in[3];
    const float* bkk  = (const float*)d_in[4];
    const float* Wck  = (const float*)d_in[5];
    const float* bck  = (const float*)d_in[6];
    const float* b_ad = (const float*)d_in[7];
    const float* Wf   = (const float*)d_in[8];
    const float* bf   = (const float*)d_in[9];
    float* out = (float*)d_out;

    float* df; float* dy;
    cudaGetSymbolAddress((void**)&df, g_f);
    cudaGetSymbolAddress((void**)&dy, g_y);

    cudaFuncSetAttribute(gemm_mma<true>,  cudaFuncAttributeMaxDynamicSharedMemorySize, SMEM_BYTES);
    cudaFuncSetAttribute(gemm_mma<false>, cudaFuncAttributeMaxDynamicSharedMemorySize, SMEM_BYTES);
    cudaFuncSetAttribute(conv_mma,        cudaFuncAttributeMaxDynamicSharedMemorySize, SMEM_BYTES);

    // 1) mean + 3x3 max pool of x
    pool_kernel<<<dim3(CC/16, NN), 256>>>(x);

    // 2) gk1 + sk
    branch_kernel<<<NN, CM>>>(Wc, bc);

    // 3) dynW
    dynw_kernel<<<dim3(KR, NN), 256>>>(Wkk, bkk, Wck, bck);

    // 4) f = relu(Wc @ x + bc): M=128, K=512  (bf16x3 mma)
    gemm_mma<true><<<dim3(HWP/128, 1, NN), 256, SMEM_BYTES>>>(
        Wc, x, df, bc, CC, (size_t)CC*HWP, (size_t)CM*HWP);

    // 5) y = dynconv(f, dynW) + b_ad  (bf16x3 mma implicit GEMM)
    conv_mma<<<dim3(HWP/128, NN), 256, SMEM_BYTES>>>(b_ad);

    // 6) out = Wf @ y + bf: M=512, K=128  (bf16x3 mma)
    gemm_mma<false><<<dim3(HWP/128, PP/128, NN), 256, SMEM_BYTES>>>(
        Wf, dy, out, bf, CM, (size_t)CM*HWP, (size_t)PP*HWP);
}

// round 7
// speedup vs baseline: 2.1725x; 1.1391x over previous
#include <cuda_runtime.h>
#include <cuda_bf16.h>
#include <cstdint>

// Problem constants
#define NN 32
#define CC 512
#define CM 128
#define HH 48
#define WW 48
#define HWP 2304
#define PP 512
#define KR 9

// ---------------- scratch (device globals; no allocation allowed) ----------
__device__ float g_mean[NN*CC];
__device__ float g_xm[NN*CC*KR];
__device__ float g_gk1[NN*CM];
__device__ float g_sk[NN*CM*KR];
// bf16-triple A-layout buffers (u32 words; 6 words per 4 fp32 k-elements)
__device__ __align__(16) uint32_t g_dynWT[(size_t)NN*KR*CM*192]; // [n][kk][o][192]
__device__ __align__(16) uint32_t g_WcT[CM*768];                 // [o][768]
__device__ __align__(16) uint32_t g_WfT[PP*192];                 // [p][192]
__device__ __align__(16) float g_f[(size_t)NN*CM*HWP];           // [n][o][hw]
__device__ __align__(16) float g_y[(size_t)NN*CM*HWP];           // [n][o][hw]

// ---------------- helpers ----------------------------------------------------
__device__ __forceinline__ uint32_t su32(const void* p){
    uint32_t a; asm("{ .reg .u64 t; cvta.to.shared.u64 t, %1; cvt.u32.u64 %0, t; }"
                    : "=r"(a) : "l"(p)); return a;
}
__device__ __forceinline__ void cpa16(uint32_t d, const void* s){
    asm volatile("cp.async.cg.shared.global [%0], [%1], 16;" :: "r"(d), "l"(s));
}
__device__ __forceinline__ void cpcommit(){ asm volatile("cp.async.commit_group;" ::: "memory"); }
template<int N> __device__ __forceinline__ void cpwait(){
    asm volatile("cp.async.wait_group %0;" :: "n"(N) : "memory");
}
// bf16 m16n8k16 MMA
__device__ __forceinline__ void mma16(float* c, const uint32_t* a, const uint32_t* b){
    asm volatile("mma.sync.aligned.m16n8k16.row.col.f32.bf16.bf16.f32 "
        "{%0,%1,%2,%3}, {%4,%5,%6,%7}, {%8,%9}, {%0,%1,%2,%3};"
        : "+f"(c[0]), "+f"(c[1]), "+f"(c[2]), "+f"(c[3])
        : "r"(a[0]), "r"(a[1]), "r"(a[2]), "r"(a[3]), "r"(b[0]), "r"(b[1]));
}
// ldmatrix x4 (b16, non-transposed)
__device__ __forceinline__ void ldmA(uint32_t* a, uint32_t saddr){
    asm volatile("ldmatrix.sync.aligned.m8n8.x4.shared.b16 {%0,%1,%2,%3}, [%4];"
      : "=r"(a[0]), "=r"(a[1]), "=r"(a[2]), "=r"(a[3]) : "r"(saddr));
}
// 2-term bf16 split: f = hi + lo (+ O(2^-17 f))
__device__ __forceinline__ void bsplit(float f, uint16_t& h, uint16_t& l){
    __nv_bfloat16 bh = __float2bfloat16(f);
    float r = f - __bfloat162float(bh);
    __nv_bfloat16 bl = __float2bfloat16(r);
    h = __bfloat16_as_ushort(bh);
    l = __bfloat16_as_ushort(bl);
}
__device__ __forceinline__ uint32_t pk(uint16_t a, uint16_t b){
    return (uint32_t)a | ((uint32_t)b << 16);
}
// A triple encode: 4 consecutive fp32 k -> 6 u32 words
__device__ __forceinline__ void storeA4(uint32_t* dst, float4 v){
    uint16_t h0,l0,h1,l1,h2,l2,h3,l3;
    bsplit(v.x, h0, l0); bsplit(v.y, h1, l1);
    bsplit(v.z, h2, l2); bsplit(v.w, h3, l3);
    *(uint2*)(dst)     = make_uint2(pk(h0,l0), pk(h0,h1));
    *(uint2*)(dst + 2) = make_uint2(pk(l1,h1), pk(h2,l2));
    *(uint2*)(dst + 4) = make_uint2(pk(h2,h3), pk(l3,h3));
}
// B triple encode: two consecutive fp32 k rows (k even), 4 cols -> 3 swizzled uint4
__device__ __forceinline__ void storeB2x4(uint32_t* bw, int wp, int bn4,
                                          const float* r0, const float* r1){
    uint32_t w0[4], w1[4], w2[4];
#pragma unroll
    for (int j = 0; j < 4; j++) {
        uint16_t H0,L0,H1,L1;
        bsplit(r0[j], H0, L0);
        bsplit(r1[j], H1, L1);
        w0[j] = pk(H0,H0); w1[j] = pk(L0,H1); w2[j] = pk(H1,L1);
    }
    *(uint4*)(bw + (wp  )*128 + (bn4 ^ (((wp  )&3)<<3))) = make_uint4(w0[0],w0[1],w0[2],w0[3]);
    *(uint4*)(bw + (wp+1)*128 + (bn4 ^ (((wp+1)&3)<<3))) = make_uint4(w1[0],w1[1],w1[2],w1[3]);
    *(uint4*)(bw + (wp+2)*128 + (bn4 ^ (((wp+2)&3)<<3))) = make_uint4(w2[0],w2[1],w2[2],w2[3]);
}

// smem geometry (u32 units). A: [128 rows][48 words + pad->52]; B: [48 words][128 cols]
#define AP 52
#define AWBUF (128*AP)          // 6656
#define BWBUF (48*128)          // 6144
#define BUFW  (AWBUF + BWBUF)   // 12800
#define SMEM_BYTES (2*BUFW*4)   // 102400

// ---------------- kernel 1: mean + 3x3 adaptive max pool (coalesced) -------
__global__ void pool_kernel(const float* __restrict__ x) {
    const int g = threadIdx.x >> 4, l = threadIdx.x & 15;
    const int c = blockIdx.x*16 + g, n = blockIdx.y;
    const float4* xp = (const float4*)(x + (size_t)(n*CC + c)*HWP);

    float s = 0.f;
    float mx[KR];
#pragma unroll
    for (int r = 0; r < KR; r++) {
        const int hb = r/3, wb = r - (r/3)*3;
        float mr = -3.402823466e38f;
#pragma unroll
        for (int j = 0; j < 4; j++) {
            int idx = j*16 + l;
            int row = idx >> 2, w4 = idx & 3;
            float4 v = xp[(hb*16 + row)*12 + wb*4 + w4];
            s += v.x + v.y + v.z + v.w;
            mr = fmaxf(mr, fmaxf(fmaxf(v.x, v.y), fmaxf(v.z, v.w)));
        }
        mx[r] = mr;
    }
#pragma unroll
    for (int o = 8; o > 0; o >>= 1) {
        s += __shfl_down_sync(0xffffffffu, s, o, 16);
#pragma unroll
        for (int r = 0; r < KR; r++)
            mx[r] = fmaxf(mx[r], __shfl_down_sync(0xffffffffu, mx[r], o, 16));
    }
    if (l == 0) {
        g_mean[n*CC + c] = s * (1.0f/(float)HWP);
#pragma unroll
        for (int r = 0; r < KR; r++) g_xm[(size_t)(n*CC + c)*KR + r] = mx[r];
    }
}

// ---------------- kernel 2: global+spatial branches (gk1, sk) --------------
__global__ void branch_kernel(const float* __restrict__ Wc, const float* __restrict__ bc) {
    int n = blockIdx.x;
    int o = threadIdx.x;
    __shared__ float sm[CC];
    __shared__ float sxm[CC*KR];
    for (int i = o; i < CC; i += CM) sm[i] = g_mean[n*CC + i];
    for (int i = o; i < CC*KR; i += CM) sxm[i] = g_xm[(size_t)n*CC*KR + i];
    __syncthreads();

    float acc0 = bc[o];
    float acc[KR];
#pragma unroll
    for (int r = 0; r < KR; r++) acc[r] = bc[o];
    const float* wr = Wc + (size_t)o*CC;
    for (int c = 0; c < CC; c++) {
        float w = __ldg(&wr[c]);
        acc0 += w * sm[c];
#pragma unroll
        for (int r = 0; r < KR; r++) acc[r] += w * sxm[c*KR + r];
    }
    g_gk1[n*CM + o] = fmaxf(acc0, 0.f);
#pragma unroll
    for (int r = 0; r < KR; r++) g_sk[(size_t)(n*CM + o)*KR + r] = fmaxf(acc[r], 0.f);
}

// ---------------- weight triple-encode (one-shot, tiny) ---------------------
// W: [M][Kd] fp32 -> T: [M][(Kd/4)*6] u32 trip layout. One thread per 4 fp32.
__global__ void wtrip_kernel(const float* __restrict__ W, uint32_t* __restrict__ T, int Kd) {
    const int idx = blockIdx.x*256 + threadIdx.x;
    const int gpr = Kd >> 2;
    const int row = idx / gpr, g = idx - row*gpr;
    float4 v = *(const float4*)(W + (size_t)row*Kd + 4*g);
    storeA4(T + (size_t)row*(gpr*6) + 6*g, v);
}

// ---------------- kernel 3: dynamic weights, emitted in trip layout ---------
__global__ void dynw_kernel(const float* __restrict__ Wkk, const float* __restrict__ bkk,
                            const float* __restrict__ Wck, const float* __restrict__ bck) {
    int r = blockIdx.x, n = blockIdx.y;
    int tid = threadIdx.x;
    __shared__ float s_gk[CM], s_sk[CM];
    if (tid < CM) {
        float gk1 = g_gk1[n*CM + tid];
        s_gk[tid] = gk1 * Wkk[r] + bkk[r];
        s_sk[tid] = g_sk[(size_t)(n*CM + tid)*KR + r];
    }
    __syncthreads();
    uint32_t* dst = g_dynWT + (size_t)(n*KR + r)*CM*192;
#pragma unroll
    for (int i = 0; i < 16; i++) {
        const int idx = tid + i*256;       // 0..4095 groups of 4 c
        const int o = idx >> 5, gc = idx & 31;
        const int c4 = gc*4;
        const float wa = Wck[o*2], wb = Wck[o*2+1], bo = bck[o];
        float4 v;
        v.x = fmaxf(wa*s_gk[c4]   + wb*s_sk[c4]   + bo, 0.f);
        v.y = fmaxf(wa*s_gk[c4+1] + wb*s_sk[c4+1] + bo, 0.f);
        v.z = fmaxf(wa*s_gk[c4+2] + wb*s_sk[c4+2] + bo, 0.f);
        v.w = fmaxf(wa*s_gk[c4+3] + wb*s_sk[c4+3] + bo, 0.f);
        storeA4(dst + (size_t)o*192 + gc*6, v);
    }
}

// ---------------- shared bf16 mma compute (ldmatrix A + LDS B) --------------
__device__ __forceinline__ void mma_compute(
    uint32_t aAddr, const uint32_t* pb, float acc[2][8][4],
    int wn, int lane)
{
    const int lq = lane >> 2, lr = lane & 3;
#pragma unroll
    for (int s = 0; s < 6; s++) {
        uint32_t a[2][4];
        ldmA(a[0], aAddr + s*32);
        ldmA(a[1], aAddr + 16*AP*4 + s*32);
        const int w0 = s*8 + lr;
        const int xr = (w0 & 3) << 3;
        const int nb = wn*64 + lq;
#pragma unroll
        for (int nt = 0; nt < 8; nt++) {
            const int col = (nb + nt*8) ^ xr;
            uint32_t b[2];
            b[0] = pb[w0*128 + col];
            b[1] = pb[(w0+4)*128 + col];
            mma16(acc[0][nt], a[0], b);
            mma16(acc[1][nt], a[1], b);
        }
    }
}

// ---------------- bf16x3 mma GEMM: C[n] = act(At @ B[n] + bias) --------------
// At: [M][(Kd/4)*6] u32 trip (shared across n). B[n]: [Kd][2304]. C[n]: [M][2304]
template<bool RELU>
__global__ void __launch_bounds__(256, 2) gemm_mma(
    const uint32_t* __restrict__ At, const float* __restrict__ B,
    float* __restrict__ C, const float* __restrict__ bias,
    int Kd, size_t BstrN, size_t CstrN)
{
    extern __shared__ uint32_t sm[];
    const uint32_t sBase = su32(sm);

    const int tid = threadIdx.x, lane = tid & 31, wid = tid >> 5;
    const int wm = wid & 3, wn = wid >> 2;
    const int n0 = blockIdx.x * 128;
    const int m0 = blockIdx.y * 128;
    const int nb = blockIdx.z;
    const int W3 = (Kd >> 2) * 6;
    const float* Bp = B + (size_t)nb*BstrN + n0;
    float*       Cp = C + (size_t)nb*CstrN;

    // B loader coords
    const int kb2 = (tid >> 5) * 2;     // B k rows kb2+16q, +1
    const int bn4 = (tid & 31) * 4;     // B cols

    // per-thread ldmatrix base (byte address, buffer 0, s=0, mt=0)
    const uint32_t aAddr0 = sBase + (uint32_t)((wm*32 + (lane & 15))*AP + (lane >> 4)*4)*4;

    float acc[2][8][4];
#pragma unroll
    for (int i = 0; i < 2; i++)
#pragma unroll
        for (int j = 0; j < 8; j++)
#pragma unroll
            for (int t = 0; t < 4; t++) acc[i][j][t] = 0.f;

    float4 rB[2][2];

    auto cpA = [&](int it){
        const int buf = it & 1;
#pragma unroll
        for (int j = 0; j < 6; j++) {
            const int ch = tid + j*256;          // 0..1535 16B chunks
            const int row = ch / 12, w16 = ch - row*12;
            cpa16(sBase + (uint32_t)(buf*BUFW + row*AP + w16*4)*4,
                  At + (size_t)(m0 + row)*W3 + it*48 + w16*4);
        }
        cpcommit();
    };
    auto ldgB = [&](int it){
        const int k0 = it * 32;
#pragma unroll
        for (int q = 0; q < 2; q++) {
            const int k = k0 + kb2 + q*16;
            rB[q][0] = *(const float4*)(Bp + (size_t)k*HWP + bn4);
            rB[q][1] = *(const float4*)(Bp + (size_t)(k+1)*HWP + bn4);
        }
    };
    auto stsB = [&](int buf){
        uint32_t* bw = sm + buf*BUFW + AWBUF;
#pragma unroll
        for (int q = 0; q < 2; q++)
            storeB2x4(bw, ((tid>>5) + q*8)*3, bn4, (const float*)&rB[q][0], (const float*)&rB[q][1]);
    };

    const int nIter = Kd / 32;
    cpA(0); ldgB(0); stsB(0); cpwait<0>(); __syncthreads();
    for (int it = 0; it < nIter; ++it) {
        const int cur = it & 1;
        if (it + 1 < nIter) { cpA(it + 1); ldgB(it + 1); }
        mma_compute(aAddr0 + cur*BUFW*4, sm + cur*BUFW + AWBUF, acc, wn, lane);
        if (it + 1 < nIter) { stsB(cur ^ 1); cpwait<0>(); __syncthreads(); }
    }

    const int lq = lane >> 2, lr = lane & 3;
#pragma unroll
    for (int mt = 0; mt < 2; mt++) {
        const int r0 = m0 + wm*32 + mt*16 + lq;
        const float bv0 = __ldg(&bias[r0]);
        const float bv1 = __ldg(&bias[r0 + 8]);
#pragma unroll
        for (int nt = 0; nt < 8; nt++) {
            const int cb = n0 + wn*64 + nt*8 + 2*lr;
            float2 v0 = make_float2(acc[mt][nt][0] + bv0, acc[mt][nt][1] + bv0);
            float2 v1 = make_float2(acc[mt][nt][2] + bv1, acc[mt][nt][3] + bv1);
            if (RELU) {
                v0.x = fmaxf(v0.x, 0.f); v0.y = fmaxf(v0.y, 0.f);
                v1.x = fmaxf(v1.x, 0.f); v1.y = fmaxf(v1.y, 0.f);
            }
            *(float2*)(Cp + (size_t)r0*HWP + cb)       = v0;
            *(float2*)(Cp + (size_t)(r0 + 8)*HWP + cb) = v1;
        }
    }
}

// ---------------- dynamic 3x3 conv as implicit GEMM (bf16x3 mma) -------------
__global__ void __launch_bounds__(256, 2) conv_mma(const float* __restrict__ b_ad)
{
    extern __shared__ uint32_t sm[];
    const uint32_t sBase = su32(sm);

    const int tid = threadIdx.x, lane = tid & 31, wid = tid >> 5;
    const int wm = wid & 3, wn = wid >> 2;
    const int hw0 = blockIdx.x * 128;
    const int nb  = blockIdx.y;
    const float* fb = g_f + (size_t)nb*CM*HWP;
    const uint32_t* dwt = g_dynWT + (size_t)nb*KR*CM*192;

    const int cb2 = (tid >> 5) * 2;     // channel rows cb2+16q, +1
    const int bn4 = (tid & 31) * 4;

    const uint32_t aAddr0 = sBase + (uint32_t)((wm*32 + (lane & 15))*AP + (lane >> 4)*4)*4;

    // per-col fixed output coords
    int oh[4], ow[4];
#pragma unroll
    for (int j = 0; j < 4; j++) {
        const int hwg = hw0 + bn4 + j;
        oh[j] = hwg / WW;
        ow[j] = hwg - oh[j]*WW;
    }

    float acc[2][8][4];
#pragma unroll
    for (int i = 0; i < 2; i++)
#pragma unroll
        for (int j = 0; j < 8; j++)
#pragma unroll
            for (int t = 0; t < 4; t++) acc[i][j][t] = 0.f;

    float rB[2][2][4];

    auto cpA = [&](int it){
        const int buf = it & 1;
        const int kk = it >> 2, c48 = (it & 3)*48;
        const uint32_t* src = dwt + (size_t)kk*CM*192;
#pragma unroll
        for (int j = 0; j < 6; j++) {
            const int ch = tid + j*256;
            const int row = ch / 12, w16 = ch - row*12;
            cpa16(sBase + (uint32_t)(buf*BUFW + row*AP + w16*4)*4,
                  src + (size_t)row*192 + c48 + w16*4);
        }
        cpcommit();
    };
    auto ldgB = [&](int it){
        const int kk = it >> 2, c0 = (it & 3) * 32;
        const int kh = kk/3 - 1, kw = kk - (kk/3)*3 - 1;
        int  off[4];
        bool ok[4];
#pragma unroll
        for (int j = 0; j < 4; j++) {
            const int hr = oh[j] + kh, wc = ow[j] + kw;
            ok[j]  = (hr >= 0) && (hr < HH) && (wc >= 0) && (wc < WW);
            off[j] = ok[j] ? (hr*WW + wc) : 0;
        }
#pragma unroll
        for (int q = 0; q < 2; q++) {
            const int c = c0 + cb2 + q*16;
#pragma unroll
            for (int j = 0; j < 4; j++) {
                rB[q][0][j] = ok[j] ? __ldg(fb + (size_t)c*HWP + off[j])     : 0.f;
                rB[q][1][j] = ok[j] ? __ldg(fb + (size_t)(c+1)*HWP + off[j]) : 0.f;
            }
        }
    };
    auto stsB = [&](int buf){
        uint32_t* bw = sm + buf*BUFW + AWBUF;
#pragma unroll
        for (int q = 0; q < 2; q++)
            storeB2x4(bw, ((tid>>5) + q*8)*3, bn4, rB[q][0], rB[q][1]);
    };

    const int nIter = KR * 4;   // 36
    cpA(0); ldgB(0); stsB(0); cpwait<0>(); __syncthreads();
    for (int it = 0; it < nIter; ++it) {
        const int cur = it & 1;
        if (it + 1 < nIter) { cpA(it + 1); ldgB(it + 1); }
        mma_compute(aAddr0 + cur*BUFW*4, sm + cur*BUFW + AWBUF, acc, wn, lane);
        if (it + 1 < nIter) { stsB(cur ^ 1); cpwait<0>(); __syncthreads(); }
    }

    const int lq = lane >> 2, lr = lane & 3;
    float* yb = g_y + (size_t)nb*CM*HWP;
#pragma unroll
    for (int mt = 0; mt < 2; mt++) {
        const int o0 = wm*32 + mt*16 + lq;
        const float bv0 = __ldg(&b_ad[o0]);
        const float bv1 = __ldg(&b_ad[o0 + 8]);
#pragma unroll
        for (int nt = 0; nt < 8; nt++) {
            const int cb = hw0 + wn*64 + nt*8 + 2*lr;
            float2 v0 = make_float2(acc[mt][nt][0] + bv0, acc[mt][nt][1] + bv0);
            float2 v1 = make_float2(acc[mt][nt][2] + bv1, acc[mt][nt][3] + bv1);
            *(float2*)(yb + (size_t)o0*HWP + cb)       = v0;
            *(float2*)(yb + (size_t)(o0 + 8)*HWP + cb) = v1;
        }
    }
}

// ---------------- launch -----------------------------------------------------
extern "C" void kernel_launch(void* const* d_in, const int* in_sizes, int n_in,
                              void* d_out, int out_size) {
    const float* x    = (const float*)d_in[0];
    const float* Wc   = (const float*)d_in[1];
    const float* bc   = (const float*)d_in[2];
    const float* Wkk  = (const float*)d_in[3];
    const float* bkk  = (const float*)d_in[4];
    const float* Wck  = (const float*)d_in[5];
    const float* bck  = (const float*)d_in[6];
    const float* b_ad = (const float*)d_in[7];
    const float* Wf   = (const float*)d_in[8];
    const float* bf   = (const float*)d_in[9];
    float* out = (float*)d_out;

    float* df; float* dy;
    uint32_t* dWcT; uint32_t* dWfT;
    cudaGetSymbolAddress((void**)&df,   g_f);
    cudaGetSymbolAddress((void**)&dy,   g_y);
    cudaGetSymbolAddress((void**)&dWcT, g_WcT);
    cudaGetSymbolAddress((void**)&dWfT, g_WfT);

    cudaFuncSetAttribute(gemm_mma<true>,  cudaFuncAttributeMaxDynamicSharedMemorySize, SMEM_BYTES);
    cudaFuncSetAttribute(gemm_mma<false>, cudaFuncAttributeMaxDynamicSharedMemorySize, SMEM_BYTES);
    cudaFuncSetAttribute(conv_mma,        cudaFuncAttributeMaxDynamicSharedMemorySize, SMEM_BYTES);

    // 0) one-shot weight triple-encodes (Wc: 128x512, Wf: 512x128)
    wtrip_kernel<<<CM*(CC/4)/256, 256>>>(Wc, dWcT, CC);
    wtrip_kernel<<<PP*(CM/4)/256, 256>>>(Wf, dWfT, CM);

    // 1) mean + 3x3 max pool of x
    pool_kernel<<<dim3(CC/16, NN), 256>>>(x);

    // 2) gk1 + sk
    branch_kernel<<<NN, CM>>>(Wc, bc);

    // 3) dynW (emitted directly in bf16-trip layout)
    dynw_kernel<<<dim3(KR, NN), 256>>>(Wkk, bkk, Wck, bck);

    // 4) f = relu(Wc @ x + bc): M=128, K=512
    gemm_mma<true><<<dim3(HWP/128, 1, NN), 256, SMEM_BYTES>>>(
        dWcT, x, df, bc, CC, (size_t)CC*HWP, (size_t)CM*HWP);

    // 5) y = dynconv(f, dynW) + b_ad
    conv_mma<<<dim3(HWP/128, NN), 256, SMEM_BYTES>>>(b_ad);

    // 6) out = Wf @ y + bf: M=512, K=128
    gemm_mma<false><<<dim3(HWP/128, PP/128, NN), 256, SMEM_BYTES>>>(
        dWfT, dy, out, bf, CM, (size_t)CM*HWP, (size_t)PP*HWP);
}

// round 9
// speedup vs baseline: 2.2705x; 1.0451x over previous
#include <cuda_runtime.h>
#include <cuda_bf16.h>
#include <cstdint>

// Problem constants
#define NN 32
#define CC 512
#define CM 128
#define HH 48
#define WW 48
#define HWP 2304
#define PP 512
#define KR 9

// ---------------- scratch (device globals; no allocation allowed) ----------
__device__ float g_pool[NN*CC*12];   // [n][c][12]: mean, 9 region-maxes, pad
__device__ float g_gk1[NN*CM];
__device__ float g_sk[NN*CM*KR];
// bf16-triple A-layout buffers (u32 words; 6 words per 4 fp32 k-elements)
__device__ __align__(16) uint32_t g_dynWT[(size_t)NN*KR*CM*192]; // [n][kk][o][192]
__device__ __align__(16) uint32_t g_WcT[CM*768];                 // [o][768]
__device__ __align__(16) uint32_t g_WfT[PP*192];                 // [p][192]
__device__ __align__(16) float g_f[(size_t)NN*CM*HWP];           // [n][o][hw]
__device__ __align__(16) float g_y[(size_t)NN*CM*HWP];           // [n][o][hw]

// ---------------- helpers ----------------------------------------------------
__device__ __forceinline__ uint32_t su32(const void* p){
    uint32_t a; asm("{ .reg .u64 t; cvta.to.shared.u64 t, %1; cvt.u32.u64 %0, t; }"
                    : "=r"(a) : "l"(p)); return a;
}
__device__ __forceinline__ void cpa16(uint32_t d, const void* s){
    asm volatile("cp.async.cg.shared.global [%0], [%1], 16;" :: "r"(d), "l"(s));
}
__device__ __forceinline__ void cpcommit(){ asm volatile("cp.async.commit_group;" ::: "memory"); }
template<int N> __device__ __forceinline__ void cpwait(){
    asm volatile("cp.async.wait_group %0;" :: "n"(N) : "memory");
}
// bf16 m16n8k16 MMA
__device__ __forceinline__ void mma16(float* c, const uint32_t* a, const uint32_t* b){
    asm volatile("mma.sync.aligned.m16n8k16.row.col.f32.bf16.bf16.f32 "
        "{%0,%1,%2,%3}, {%4,%5,%6,%7}, {%8,%9}, {%0,%1,%2,%3};"
        : "+f"(c[0]), "+f"(c[1]), "+f"(c[2]), "+f"(c[3])
        : "r"(a[0]), "r"(a[1]), "r"(a[2]), "r"(a[3]), "r"(b[0]), "r"(b[1]));
}
// ldmatrix x4 (b16, non-transposed)
__device__ __forceinline__ void ldmA(uint32_t* a, uint32_t saddr){
    asm volatile("ldmatrix.sync.aligned.m8n8.x4.shared.b16 {%0,%1,%2,%3}, [%4];"
      : "=r"(a[0]), "=r"(a[1]), "=r"(a[2]), "=r"(a[3]) : "r"(saddr));
}
// 2-term bf16 split: f = hi + lo (+ O(2^-17 f))
__device__ __forceinline__ void bsplit(float f, uint16_t& h, uint16_t& l){
    __nv_bfloat16 bh = __float2bfloat16(f);
    float r = f - __bfloat162float(bh);
    __nv_bfloat16 bl = __float2bfloat16(r);
    h = __bfloat16_as_ushort(bh);
    l = __bfloat16_as_ushort(bl);
}
__device__ __forceinline__ uint32_t pk(uint16_t a, uint16_t b){
    return (uint32_t)a | ((uint32_t)b << 16);
}
// A triple encode: 4 consecutive fp32 k -> 6 u32 words
__device__ __forceinline__ void storeA4(uint32_t* dst, float4 v){
    uint16_t h0,l0,h1,l1,h2,l2,h3,l3;
    bsplit(v.x, h0, l0); bsplit(v.y, h1, l1);
    bsplit(v.z, h2, l2); bsplit(v.w, h3, l3);
    *(uint2*)(dst)     = make_uint2(pk(h0,l0), pk(h0,h1));
    *(uint2*)(dst + 2) = make_uint2(pk(l1,h1), pk(h2,l2));
    *(uint2*)(dst + 4) = make_uint2(pk(h2,h3), pk(l3,h3));
}
// B triple encode: two consecutive fp32 k rows (k even), 4 cols -> 3 swizzled uint4
__device__ __forceinline__ void storeB2x4(uint32_t* bw, int wp, int bn4,
                                          const float* r0, const float* r1){
    uint32_t w0[4], w1[4], w2[4];
#pragma unroll
    for (int j = 0; j < 4; j++) {
        uint16_t H0,L0,H1,L1;
        bsplit(r0[j], H0, L0);
        bsplit(r1[j], H1, L1);
        w0[j] = pk(H0,H0); w1[j] = pk(L0,H1); w2[j] = pk(H1,L1);
    }
    *(uint4*)(bw + (wp  )*128 + (bn4 ^ (((wp  )&3)<<3))) = make_uint4(w0[0],w0[1],w0[2],w0[3]);
    *(uint4*)(bw + (wp+1)*128 + (bn4 ^ (((wp+1)&3)<<3))) = make_uint4(w1[0],w1[1],w1[2],w1[3]);
    *(uint4*)(bw + (wp+2)*128 + (bn4 ^ (((wp+2)&3)<<3))) = make_uint4(w2[0],w2[1],w2[2],w2[3]);
}

// smem geometry (u32 units). A: [128 rows][48 words + pad->52]; B: [48 words][128 cols]
#define AP 52
#define AWBUF (128*AP)          // 6656
#define BWBUF (48*128)          // 6144
#define BUFW  (AWBUF + BWBUF)   // 12800
#define SMEM_BYTES (2*BUFW*4)   // 102400

// ---------------- kernel 1: mean + 3x3 adaptive max pool (coalesced) -------
// writes g_pool[n][c][12] = {mean, max r0..r8, 0, 0}
__global__ void pool_kernel(const float* __restrict__ x) {
    const int g = threadIdx.x >> 4, l = threadIdx.x & 15;
    const int c = blockIdx.x*16 + g, n = blockIdx.y;
    const float4* xp = (const float4*)(x + (size_t)(n*CC + c)*HWP);

    float s = 0.f;
    float mx[KR];
#pragma unroll
    for (int r = 0; r < KR; r++) {
        const int hb = r/3, wb = r - (r/3)*3;
        float mr = -3.402823466e38f;
#pragma unroll
        for (int j = 0; j < 4; j++) {
            int idx = j*16 + l;
            int row = idx >> 2, w4 = idx & 3;
            float4 v = xp[(hb*16 + row)*12 + wb*4 + w4];
            s += v.x + v.y + v.z + v.w;
            mr = fmaxf(mr, fmaxf(fmaxf(v.x, v.y), fmaxf(v.z, v.w)));
        }
        mx[r] = mr;
    }
#pragma unroll
    for (int o = 8; o > 0; o >>= 1) {
        s += __shfl_down_sync(0xffffffffu, s, o, 16);
#pragma unroll
        for (int r = 0; r < KR; r++)
            mx[r] = fmaxf(mx[r], __shfl_down_sync(0xffffffffu, mx[r], o, 16));
    }
    if (l == 0) {
        float* dst = g_pool + (size_t)(n*CC + c)*12;
        dst[0] = s * (1.0f/(float)HWP);
#pragma unroll
        for (int r = 0; r < KR; r++) dst[1+r] = mx[r];
        dst[10] = 0.f; dst[11] = 0.f;
    }
}

// ---------------- kernel 2: branches (warp-parallel) ------------------------
// block = n (32 blocks), 256 threads = 8 warps; each warp owns 16 o-channels.
__global__ void __launch_bounds__(256) branch_kernel(
    const float* __restrict__ Wc, const float* __restrict__ bc) {
    const int n = blockIdx.x;
    const int tid = threadIdx.x, lane = tid & 31, w = tid >> 5;
    __shared__ __align__(16) float sp[CC*12];
    const float4* src = (const float4*)(g_pool + (size_t)n*CC*12);
    float4* dst4 = (float4*)sp;
    for (int i = tid; i < CC*3; i += 256) dst4[i] = src[i];
    __syncthreads();

#pragma unroll
    for (int ot = 0; ot < 16; ot++) {
        const int o = w*16 + ot;
        const float* wr = Wc + (size_t)o*CC;
        float acc[10];
#pragma unroll
        for (int j = 0; j < 10; j++) acc[j] = 0.f;
#pragma unroll
        for (int i = 0; i < 16; i++) {
            const int c = lane + i*32;
            const float wv = __ldg(&wr[c]);
            const float4* pc = (const float4*)(sp + c*12);
            float4 p0 = pc[0], p1 = pc[1], p2 = pc[2];
            acc[0] += wv*p0.x; acc[1] += wv*p0.y; acc[2] += wv*p0.z; acc[3] += wv*p0.w;
            acc[4] += wv*p1.x; acc[5] += wv*p1.y; acc[6] += wv*p1.z; acc[7] += wv*p1.w;
            acc[8] += wv*p2.x; acc[9] += wv*p2.y;
        }
#pragma unroll
        for (int off = 16; off > 0; off >>= 1)
#pragma unroll
            for (int j = 0; j < 10; j++)
                acc[j] += __shfl_down_sync(0xffffffffu, acc[j], off);
        if (lane == 0) {
            const float bv = bc[o];
            g_gk1[n*CM + o] = fmaxf(acc[0] + bv, 0.f);
#pragma unroll
            for (int r = 0; r < KR; r++)
                g_sk[(size_t)(n*CM + o)*KR + r] = fmaxf(acc[1+r] + bv, 0.f);
        }
    }
}

// ---------------- weight triple-encode (one-shot, tiny) ---------------------
__global__ void wtrip_kernel(const float* __restrict__ W, uint32_t* __restrict__ T, int Kd) {
    const int idx = blockIdx.x*256 + threadIdx.x;
    const int gpr = Kd >> 2;
    const int row = idx / gpr, g = idx - row*gpr;
    float4 v = *(const float4*)(W + (size_t)row*Kd + 4*g);
    storeA4(T + (size_t)row*(gpr*6) + 6*g, v);
}

// ---------------- kernel 3: dynamic weights, emitted in trip layout ---------
__global__ void dynw_kernel(const float* __restrict__ Wkk, const float* __restrict__ bkk,
                            const float* __restrict__ Wck, const float* __restrict__ bck) {
    int r = blockIdx.x, n = blockIdx.y;
    int tid = threadIdx.x;
    __shared__ float s_gk[CM], s_sk[CM];
    if (tid < CM) {
        float gk1 = g_gk1[n*CM + tid];
        s_gk[tid] = gk1 * Wkk[r] + bkk[r];
        s_sk[tid] = g_sk[(size_t)(n*CM + tid)*KR + r];
    }
    __syncthreads();
    uint32_t* dst = g_dynWT + (size_t)(n*KR + r)*CM*192;
#pragma unroll
    for (int i = 0; i < 16; i++) {
        const int idx = tid + i*256;
        const int o = idx >> 5, gc = idx & 31;
        const int c4 = gc*4;
        const float wa = Wck[o*2], wb = Wck[o*2+1], bo = bck[o];
        float4 v;
        v.x = fmaxf(wa*s_gk[c4]   + wb*s_sk[c4]   + bo, 0.f);
        v.y = fmaxf(wa*s_gk[c4+1] + wb*s_sk[c4+1] + bo, 0.f);
        v.z = fmaxf(wa*s_gk[c4+2] + wb*s_sk[c4+2] + bo, 0.f);
        v.w = fmaxf(wa*s_gk[c4+3] + wb*s_sk[c4+3] + bo, 0.f);
        storeA4(dst + (size_t)o*192 + gc*6, v);
    }
}

// ---------------- shared bf16 mma compute (ldmatrix A + LDS B) --------------
__device__ __forceinline__ void mma_compute(
    uint32_t aAddr, const uint32_t* pb, float acc[2][8][4],
    int wn, int lane)
{
    const int lq = lane >> 2, lr = lane & 3;
#pragma unroll
    for (int s = 0; s < 6; s++) {
        uint32_t a[2][4];
        ldmA(a[0], aAddr + s*32);
        ldmA(a[1], aAddr + 16*AP*4 + s*32);
        const int w0 = s*8 + lr;
        const int xr = (w0 & 3) << 3;
        const int nb = wn*64 + lq;
#pragma unroll
        for (int nt = 0; nt < 8; nt++) {
            const int col = (nb + nt*8) ^ xr;
            uint32_t b[2];
            b[0] = pb[w0*128 + col];
            b[1] = pb[(w0+4)*128 + col];
            mma16(acc[0][nt], a[0], b);
            mma16(acc[1][nt], a[1], b);
        }
    }
}

// ---------------- bf16x3 mma GEMM: C[n] = act(At @ B[n] + bias) --------------
template<bool RELU>
__global__ void __launch_bounds__(256, 2) gemm_mma(
    const uint32_t* __restrict__ At, const float* __restrict__ B,
    float* __restrict__ C, const float* __restrict__ bias,
    int Kd, size_t BstrN, size_t CstrN)
{
    extern __shared__ uint32_t sm[];
    const uint32_t sBase = su32(sm);

    const int tid = threadIdx.x, lane = tid & 31, wid = tid >> 5;
    const int wm = wid & 3, wn = wid >> 2;
    const int n0 = blockIdx.x * 128;
    const int m0 = blockIdx.y * 128;
    const int nb = blockIdx.z;
    const int W3 = (Kd >> 2) * 6;
    const float* Bp = B + (size_t)nb*BstrN + n0;
    float*       Cp = C + (size_t)nb*CstrN;

    const int kb2 = (tid >> 5) * 2;
    const int bn4 = (tid & 31) * 4;

    const uint32_t aAddr0 = sBase + (uint32_t)((wm*32 + (lane & 15))*AP + (lane >> 4)*4)*4;

    float acc[2][8][4];
#pragma unroll
    for (int i = 0; i < 2; i++)
#pragma unroll
        for (int j = 0; j < 8; j++)
#pragma unroll
            for (int t = 0; t < 4; t++) acc[i][j][t] = 0.f;

    float4 rB[2][2];

    auto cpA = [&](int it){
        const int buf = it & 1;
#pragma unroll
        for (int j = 0; j < 6; j++) {
            const int ch = tid + j*256;
            const int row = ch / 12, w16 = ch - row*12;
            cpa16(sBase + (uint32_t)(buf*BUFW + row*AP + w16*4)*4,
                  At + (size_t)(m0 + row)*W3 + it*48 + w16*4);
        }
        cpcommit();
    };
    auto ldgB = [&](int it){
        const int k0 = it * 32;
#pragma unroll
        for (int q = 0; q < 2; q++) {
            const int k = k0 + kb2 + q*16;
            rB[q][0] = *(const float4*)(Bp + (size_t)k*HWP + bn4);
            rB[q][1] = *(const float4*)(Bp + (size_t)(k+1)*HWP + bn4);
        }
    };
    auto stsB = [&](int buf){
        uint32_t* bw = sm + buf*BUFW + AWBUF;
#pragma unroll
        for (int q = 0; q < 2; q++)
            storeB2x4(bw, ((tid>>5) + q*8)*3, bn4, (const float*)&rB[q][0], (const float*)&rB[q][1]);
    };

    const int nIter = Kd / 32;
    cpA(0); ldgB(0); stsB(0); cpwait<0>(); __syncthreads();
    for (int it = 0; it < nIter; ++it) {
        const int cur = it & 1;
        if (it + 1 < nIter) { cpA(it + 1); ldgB(it + 1); }
        mma_compute(aAddr0 + cur*BUFW*4, sm + cur*BUFW + AWBUF, acc, wn, lane);
        if (it + 1 < nIter) { stsB(cur ^ 1); cpwait<0>(); __syncthreads(); }
    }

    const int lq = lane >> 2, lr = lane & 3;
#pragma unroll
    for (int mt = 0; mt < 2; mt++) {
        const int r0 = m0 + wm*32 + mt*16 + lq;
        const float bv0 = __ldg(&bias[r0]);
        const float bv1 = __ldg(&bias[r0 + 8]);
#pragma unroll
        for (int nt = 0; nt < 8; nt++) {
            const int cb = n0 + wn*64 + nt*8 + 2*lr;
            float2 v0 = make_float2(acc[mt][nt][0] + bv0, acc[mt][nt][1] + bv0);
            float2 v1 = make_float2(acc[mt][nt][2] + bv1, acc[mt][nt][3] + bv1);
            if (RELU) {
                v0.x = fmaxf(v0.x, 0.f); v0.y = fmaxf(v0.y, 0.f);
                v1.x = fmaxf(v1.x, 0.f); v1.y = fmaxf(v1.y, 0.f);
            }
            *(float2*)(Cp + (size_t)r0*HWP + cb)       = v0;
            *(float2*)(Cp + (size_t)(r0 + 8)*HWP + cb) = v1;
        }
    }
}

// ---------------- dynamic 3x3 conv as implicit GEMM (bf16x3 mma) -------------
__global__ void __launch_bounds__(256, 2) conv_mma(const float* __restrict__ b_ad)
{
    extern __shared__ uint32_t sm[];
    const uint32_t sBase = su32(sm);

    const int tid = threadIdx.x, lane = tid & 31, wid = tid >> 5;
    const int wm = wid & 3, wn = wid >> 2;
    const int hw0 = blockIdx.x * 128;
    const int nb  = blockIdx.y;
    const float* fb = g_f + (size_t)nb*CM*HWP;
    const uint32_t* dwt = g_dynWT + (size_t)nb*KR*CM*192;

    const int cb2 = (tid >> 5) * 2;
    const int bn4 = (tid & 31) * 4;

    const uint32_t aAddr0 = sBase + (uint32_t)((wm*32 + (lane & 15))*AP + (lane >> 4)*4)*4;

    // 4-col group shares one spatial row (48 % 4 == 0)
    const int hwg = hw0 + bn4;
    const int oh0 = hwg / WW;
    const int ow0 = hwg - oh0*WW;

    float acc[2][8][4];
#pragma unroll
    for (int i = 0; i < 2; i++)
#pragma unroll
        for (int j = 0; j < 8; j++)
#pragma unroll
            for (int t = 0; t < 4; t++) acc[i][j][t] = 0.f;

    float rB[2][2][4];

    auto cpA = [&](int it){
        const int buf = it & 1;
        const int kk = it >> 2, c48 = (it & 3)*48;
        const uint32_t* src = dwt + (size_t)kk*CM*192;
#pragma unroll
        for (int j = 0; j < 6; j++) {
            const int ch = tid + j*256;
            const int row = ch / 12, w16 = ch - row*12;
            cpa16(sBase + (uint32_t)(buf*BUFW + row*AP + w16*4)*4,
                  src + (size_t)row*192 + c48 + w16*4);
        }
        cpcommit();
    };
    auto ldgB = [&](int it){
        const int kk = it >> 2, c0 = (it & 3) * 32;
        const int kh = kk/3 - 1, kw = kk - (kk/3)*3 - 1;
        const int hr = oh0 + kh;
        const bool rowok = (hr >= 0) && (hr < HH);
        if (kw == 0) {
            // 16B-aligned vector path (ow0 is 4-aligned, always in-bounds)
            if (rowok) {
                const float* fp = fb + hr*WW + ow0;
#pragma unroll
                for (int q = 0; q < 2; q++) {
                    const int c = c0 + cb2 + q*16;
                    *(float4*)rB[q][0] = *(const float4*)(fp + (size_t)c*HWP);
                    *(float4*)rB[q][1] = *(const float4*)(fp + (size_t)(c+1)*HWP);
                }
            } else {
#pragma unroll
                for (int q = 0; q < 2; q++)
#pragma unroll
                    for (int j = 0; j < 4; j++) { rB[q][0][j] = 0.f; rB[q][1][j] = 0.f; }
            }
        } else {
            // scalar path with per-column predication (kw = +/-1)
            const int wc0 = ow0 + kw;
#pragma unroll
            for (int q = 0; q < 2; q++) {
                const int c = c0 + cb2 + q*16;
#pragma unroll
                for (int j = 0; j < 4; j++) {
                    const int wc = wc0 + j;
                    const bool ok = rowok && (wc >= 0) && (wc < WW);
                    const int off = ok ? (hr*WW + wc) : 0;
                    rB[q][0][j] = ok ? __ldg(fb + (size_t)c*HWP + off)     : 0.f;
                    rB[q][1][j] = ok ? __ldg(fb + (size_t)(c+1)*HWP + off) : 0.f;
                }
            }
        }
    };
    auto stsB = [&](int buf){
        uint32_t* bw = sm + buf*BUFW + AWBUF;
#pragma unroll
        for (int q = 0; q < 2; q++)
            storeB2x4(bw, ((tid>>5) + q*8)*3, bn4, rB[q][0], rB[q][1]);
    };

    const int nIter = KR * 4;   // 36
    cpA(0); ldgB(0); stsB(0); cpwait<0>(); __syncthreads();
    for (int it = 0; it < nIter; ++it) {
        const int cur = it & 1;
        if (it + 1 < nIter) { cpA(it + 1); ldgB(it + 1); }
        mma_compute(aAddr0 + cur*BUFW*4, sm + cur*BUFW + AWBUF, acc, wn, lane);
        if (it + 1 < nIter) { stsB(cur ^ 1); cpwait<0>(); __syncthreads(); }
    }

    const int lq = lane >> 2, lr = lane & 3;
    float* yb = g_y + (size_t)nb*CM*HWP;
#pragma unroll
    for (int mt = 0; mt < 2; mt++) {
        const int o0 = wm*32 + mt*16 + lq;
        const float bv0 = __ldg(&b_ad[o0]);
        const float bv1 = __ldg(&b_ad[o0 + 8]);
#pragma unroll
        for (int nt = 0; nt < 8; nt++) {
            const int cb = hw0 + wn*64 + nt*8 + 2*lr;
            float2 v0 = make_float2(acc[mt][nt][0] + bv0, acc[mt][nt][1] + bv0);
            float2 v1 = make_float2(acc[mt][nt][2] + bv1, acc[mt][nt][3] + bv1);
            *(float2*)(yb + (size_t)o0*HWP + cb)       = v0;
            *(float2*)(yb + (size_t)(o0 + 8)*HWP + cb) = v1;
        }
    }
}

// ---------------- launch -----------------------------------------------------
extern "C" void kernel_launch(void* const* d_in, const int* in_sizes, int n_in,
                              void* d_out, int out_size) {
    const float* x    = (const float*)d_in[0];
    const float* Wc   = (const float*)d_in[1];
    const float* bc   = (const float*)d_in[2];
    const float* Wkk  = (const float*)d_in[3];
    const float* bkk  = (const float*)d_in[4];
    const float* Wck  = (const float*)d_in[5];
    const float* bck  = (const float*)d_in[6];
    const float* b_ad = (const float*)d_in[7];
    const float* Wf   = (const float*)d_in[8];
    const float* bf   = (const float*)d_in[9];
    float* out = (float*)d_out;

    float* df; float* dy;
    uint32_t* dWcT; uint32_t* dWfT;
    cudaGetSymbolAddress((void**)&df,   g_f);
    cudaGetSymbolAddress((void**)&dy,   g_y);
    cudaGetSymbolAddress((void**)&dWcT, g_WcT);
    cudaGetSymbolAddress((void**)&dWfT, g_WfT);

    cudaFuncSetAttribute(gemm_mma<true>,  cudaFuncAttributeMaxDynamicSharedMemorySize, SMEM_BYTES);
    cudaFuncSetAttribute(gemm_mma<false>, cudaFuncAttributeMaxDynamicSharedMemorySize, SMEM_BYTES);
    cudaFuncSetAttribute(conv_mma,        cudaFuncAttributeMaxDynamicSharedMemorySize, SMEM_BYTES);

    // 0) one-shot weight triple-encodes
    wtrip_kernel<<<CM*(CC/4)/256, 256>>>(Wc, dWcT, CC);
    wtrip_kernel<<<PP*(CM/4)/256, 256>>>(Wf, dWfT, CM);

    // 1) mean + 3x3 max pool of x -> g_pool[n][c][12]
    pool_kernel<<<dim3(CC/16, NN), 256>>>(x);

    // 2) gk1 + sk (warp-parallel)
    branch_kernel<<<NN, 256>>>(Wc, bc);

    // 3) dynW (bf16-trip layout)
    dynw_kernel<<<dim3(KR, NN), 256>>>(Wkk, bkk, Wck, bck);

    // 4) f = relu(Wc @ x + bc): M=128, K=512
    gemm_mma<true><<<dim3(HWP/128, 1, NN), 256, SMEM_BYTES>>>(
        dWcT, x, df, bc, CC, (size_t)CC*HWP, (size_t)CM*HWP);

    // 5) y = dynconv(f, dynW) + b_ad
    conv_mma<<<dim3(HWP/128, NN), 256, SMEM_BYTES>>>(b_ad);

    // 6) out = Wf @ y + bf: M=512, K=128
    gemm_mma<false><<<dim3(HWP/128, PP/128, NN), 256, SMEM_BYTES>>>(
        dWfT, dy, out, bf, CM, (size_t)CM*HWP, (size_t)PP*HWP);
}

// round 10
// speedup vs baseline: 2.3876x; 1.0516x over previous
#include <cuda_runtime.h>
#include <cuda_bf16.h>
#include <cstdint>

// Problem constants
#define NN 32
#define CC 512
#define CM 128
#define HH 48
#define WW 48
#define HWP 2304
#define PP 512
#define KR 9

// ---------------- scratch (device globals; no allocation allowed) ----------
__device__ float g_pool[NN*CC*12];   // [n][c][12]: mean, 9 region-maxes, pad
__device__ float g_gk1[NN*CM];
__device__ float g_sk[NN*CM*KR];
// bf16-triple A-layout buffers (u32 words; 6 words per 4 fp32 k-elements)
__device__ __align__(16) uint32_t g_dynWT[(size_t)NN*KR*CM*192]; // [n][kk][o][192]
__device__ __align__(16) uint32_t g_WcT[CM*768];                 // [o][768]
__device__ __align__(16) uint32_t g_WfT[PP*192];                 // [p][192]
__device__ __align__(16) float g_f[(size_t)NN*CM*HWP];           // [n][o][hw]
__device__ __align__(16) float g_y[(size_t)NN*CM*HWP];           // [n][o][hw]

// ---------------- helpers ----------------------------------------------------
__device__ __forceinline__ uint32_t su32(const void* p){
    uint32_t a; asm("{ .reg .u64 t; cvta.to.shared.u64 t, %1; cvt.u32.u64 %0, t; }"
                    : "=r"(a) : "l"(p)); return a;
}
__device__ __forceinline__ void cpa16(uint32_t d, const void* s){
    asm volatile("cp.async.cg.shared.global [%0], [%1], 16;" :: "r"(d), "l"(s));
}
__device__ __forceinline__ void cpcommit(){ asm volatile("cp.async.commit_group;" ::: "memory"); }
template<int N> __device__ __forceinline__ void cpwait(){
    asm volatile("cp.async.wait_group %0;" :: "n"(N) : "memory");
}
// bf16 m16n8k16 MMA
__device__ __forceinline__ void mma16(float* c, const uint32_t* a, const uint32_t* b){
    asm volatile("mma.sync.aligned.m16n8k16.row.col.f32.bf16.bf16.f32 "
        "{%0,%1,%2,%3}, {%4,%5,%6,%7}, {%8,%9}, {%0,%1,%2,%3};"
        : "+f"(c[0]), "+f"(c[1]), "+f"(c[2]), "+f"(c[3])
        : "r"(a[0]), "r"(a[1]), "r"(a[2]), "r"(a[3]), "r"(b[0]), "r"(b[1]));
}
// ldmatrix x4 (b16, non-transposed)
__device__ __forceinline__ void ldmA(uint32_t* a, uint32_t saddr){
    asm volatile("ldmatrix.sync.aligned.m8n8.x4.shared.b16 {%0,%1,%2,%3}, [%4];"
      : "=r"(a[0]), "=r"(a[1]), "=r"(a[2]), "=r"(a[3]) : "r"(saddr));
}
// 2-term bf16 split: f = hi + lo (+ O(2^-17 f))
__device__ __forceinline__ void bsplit(float f, uint16_t& h, uint16_t& l){
    __nv_bfloat16 bh = __float2bfloat16(f);
    float r = f - __bfloat162float(bh);
    __nv_bfloat16 bl = __float2bfloat16(r);
    h = __bfloat16_as_ushort(bh);
    l = __bfloat16_as_ushort(bl);
}
__device__ __forceinline__ uint32_t pk(uint16_t a, uint16_t b){
    return (uint32_t)a | ((uint32_t)b << 16);
}
// A triple encode: 4 consecutive fp32 k -> 6 u32 words
__device__ __forceinline__ void storeA4(uint32_t* dst, float4 v){
    uint16_t h0,l0,h1,l1,h2,l2,h3,l3;
    bsplit(v.x, h0, l0); bsplit(v.y, h1, l1);
    bsplit(v.z, h2, l2); bsplit(v.w, h3, l3);
    *(uint2*)(dst)     = make_uint2(pk(h0,l0), pk(h0,h1));
    *(uint2*)(dst + 2) = make_uint2(pk(l1,h1), pk(h2,l2));
    *(uint2*)(dst + 4) = make_uint2(pk(h2,h3), pk(l3,h3));
}
// B triple encode: two consecutive fp32 k rows (k even), 4 cols -> 3 swizzled uint4
__device__ __forceinline__ void storeB2x4(uint32_t* bw, int wp, int bn4,
                                          const float* r0, const float* r1){
    uint32_t w0[4], w1[4], w2[4];
#pragma unroll
    for (int j = 0; j < 4; j++) {
        uint16_t H0,L0,H1,L1;
        bsplit(r0[j], H0, L0);
        bsplit(r1[j], H1, L1);
        w0[j] = pk(H0,H0); w1[j] = pk(L0,H1); w2[j] = pk(H1,L1);
    }
    *(uint4*)(bw + (wp  )*128 + (bn4 ^ (((wp  )&3)<<3))) = make_uint4(w0[0],w0[1],w0[2],w0[3]);
    *(uint4*)(bw + (wp+1)*128 + (bn4 ^ (((wp+1)&3)<<3))) = make_uint4(w1[0],w1[1],w1[2],w1[3]);
    *(uint4*)(bw + (wp+2)*128 + (bn4 ^ (((wp+2)&3)<<3))) = make_uint4(w2[0],w2[1],w2[2],w2[3]);
}

// smem geometry (u32 units). A: [128 rows][48 words + pad->52]; B: [48 words][128 cols]
#define AP 52
#define AWBUF (128*AP)          // 6656
#define BWBUF (48*128)          // 6144
#define BUFW  (AWBUF + BWBUF)   // 12800
#define SMEM_BYTES (2*BUFW*4)   // 102400

// ---------------- kernel 1: mean + 3x3 adaptive max pool (coalesced) -------
// writes g_pool[n][c][12] = {mean, max r0..r8, 0, 0}
__global__ void pool_kernel(const float* __restrict__ x) {
    const int g = threadIdx.x >> 4, l = threadIdx.x & 15;
    const int c = blockIdx.x*16 + g, n = blockIdx.y;
    const float4* xp = (const float4*)(x + (size_t)(n*CC + c)*HWP);

    float s = 0.f;
    float mx[KR];
#pragma unroll
    for (int r = 0; r < KR; r++) {
        const int hb = r/3, wb = r - (r/3)*3;
        float mr = -3.402823466e38f;
#pragma unroll
        for (int j = 0; j < 4; j++) {
            int idx = j*16 + l;
            int row = idx >> 2, w4 = idx & 3;
            float4 v = xp[(hb*16 + row)*12 + wb*4 + w4];
            s += v.x + v.y + v.z + v.w;
            mr = fmaxf(mr, fmaxf(fmaxf(v.x, v.y), fmaxf(v.z, v.w)));
        }
        mx[r] = mr;
    }
#pragma unroll
    for (int o = 8; o > 0; o >>= 1) {
        s += __shfl_down_sync(0xffffffffu, s, o, 16);
#pragma unroll
        for (int r = 0; r < KR; r++)
            mx[r] = fmaxf(mx[r], __shfl_down_sync(0xffffffffu, mx[r], o, 16));
    }
    if (l == 0) {
        float* dst = g_pool + (size_t)(n*CC + c)*12;
        dst[0] = s * (1.0f/(float)HWP);
#pragma unroll
        for (int r = 0; r < KR; r++) dst[1+r] = mx[r];
        dst[10] = 0.f; dst[11] = 0.f;
    }
}

// ---------------- kernel 2: branches (full-chip parallel) -------------------
// grid (8 og, 32 n), 256 threads = 8 warps; warp w owns o = og*16 + w*2 + {0,1}.
// lanes stripe c; reads g_pool/W directly (L2-resident); shuffle reduce.
__global__ void __launch_bounds__(256) branch_kernel(
    const float* __restrict__ Wc, const float* __restrict__ bc) {
    const int og = blockIdx.x, n = blockIdx.y;
    const int lane = threadIdx.x & 31, w = threadIdx.x >> 5;
    const int o0 = og*16 + w*2;
    const int o1 = o0 + 1;

    const float* pb = g_pool + (size_t)n*CC*12;
    const float* wr0 = Wc + (size_t)o0*CC;
    const float* wr1 = Wc + (size_t)o1*CC;

    float a0[10], a1[10];
#pragma unroll
    for (int j = 0; j < 10; j++) { a0[j] = 0.f; a1[j] = 0.f; }

#pragma unroll
    for (int i = 0; i < 16; i++) {
        const int c = lane + i*32;
        const float wv0 = __ldg(&wr0[c]);
        const float wv1 = __ldg(&wr1[c]);
        const float4* pc = (const float4*)(pb + c*12);
        float4 p0 = __ldg(pc), p1 = __ldg(pc+1), p2 = __ldg(pc+2);
        a0[0] += wv0*p0.x; a0[1] += wv0*p0.y; a0[2] += wv0*p0.z; a0[3] += wv0*p0.w;
        a0[4] += wv0*p1.x; a0[5] += wv0*p1.y; a0[6] += wv0*p1.z; a0[7] += wv0*p1.w;
        a0[8] += wv0*p2.x; a0[9] += wv0*p2.y;
        a1[0] += wv1*p0.x; a1[1] += wv1*p0.y; a1[2] += wv1*p0.z; a1[3] += wv1*p0.w;
        a1[4] += wv1*p1.x; a1[5] += wv1*p1.y; a1[6] += wv1*p1.z; a1[7] += wv1*p1.w;
        a1[8] += wv1*p2.x; a1[9] += wv1*p2.y;
    }
#pragma unroll
    for (int off = 16; off > 0; off >>= 1)
#pragma unroll
        for (int j = 0; j < 10; j++) {
            a0[j] += __shfl_down_sync(0xffffffffu, a0[j], off);
            a1[j] += __shfl_down_sync(0xffffffffu, a1[j], off);
        }
    if (lane == 0) {
        const float bv0 = bc[o0], bv1 = bc[o1];
        g_gk1[n*CM + o0] = fmaxf(a0[0] + bv0, 0.f);
        g_gk1[n*CM + o1] = fmaxf(a1[0] + bv1, 0.f);
#pragma unroll
        for (int r = 0; r < KR; r++) {
            g_sk[(size_t)(n*CM + o0)*KR + r] = fmaxf(a0[1+r] + bv0, 0.f);
            g_sk[(size_t)(n*CM + o1)*KR + r] = fmaxf(a1[1+r] + bv1, 0.f);
        }
    }
}

// ---------------- weight triple-encode (one-shot, tiny) ---------------------
__global__ void wtrip_kernel(const float* __restrict__ W, uint32_t* __restrict__ T, int Kd) {
    const int idx = blockIdx.x*256 + threadIdx.x;
    const int gpr = Kd >> 2;
    const int row = idx / gpr, g = idx - row*gpr;
    float4 v = *(const float4*)(W + (size_t)row*Kd + 4*g);
    storeA4(T + (size_t)row*(gpr*6) + 6*g, v);
}

// ---------------- kernel 3: dynamic weights, emitted in trip layout ---------
__global__ void dynw_kernel(const float* __restrict__ Wkk, const float* __restrict__ bkk,
                            const float* __restrict__ Wck, const float* __restrict__ bck) {
    int r = blockIdx.x, n = blockIdx.y;
    int tid = threadIdx.x;
    __shared__ float s_gk[CM], s_sk[CM];
    if (tid < CM) {
        float gk1 = g_gk1[n*CM + tid];
        s_gk[tid] = gk1 * Wkk[r] + bkk[r];
        s_sk[tid] = g_sk[(size_t)(n*CM + tid)*KR + r];
    }
    __syncthreads();
    uint32_t* dst = g_dynWT + (size_t)(n*KR + r)*CM*192;
#pragma unroll
    for (int i = 0; i < 16; i++) {
        const int idx = tid + i*256;
        const int o = idx >> 5, gc = idx & 31;
        const int c4 = gc*4;
        const float wa = Wck[o*2], wb = Wck[o*2+1], bo = bck[o];
        float4 v;
        v.x = fmaxf(wa*s_gk[c4]   + wb*s_sk[c4]   + bo, 0.f);
        v.y = fmaxf(wa*s_gk[c4+1] + wb*s_sk[c4+1] + bo, 0.f);
        v.z = fmaxf(wa*s_gk[c4+2] + wb*s_sk[c4+2] + bo, 0.f);
        v.w = fmaxf(wa*s_gk[c4+3] + wb*s_sk[c4+3] + bo, 0.f);
        storeA4(dst + (size_t)o*192 + gc*6, v);
    }
}

// ---------------- shared bf16 mma compute (ldmatrix A + LDS B) --------------
__device__ __forceinline__ void mma_compute(
    uint32_t aAddr, const uint32_t* pb, float acc[2][8][4],
    int wn, int lane)
{
    const int lq = lane >> 2, lr = lane & 3;
#pragma unroll
    for (int s = 0; s < 6; s++) {
        uint32_t a[2][4];
        ldmA(a[0], aAddr + s*32);
        ldmA(a[1], aAddr + 16*AP*4 + s*32);
        const int w0 = s*8 + lr;
        const int xr = (w0 & 3) << 3;
        const int nb = wn*64 + lq;
#pragma unroll
        for (int nt = 0; nt < 8; nt++) {
            const int col = (nb + nt*8) ^ xr;
            uint32_t b[2];
            b[0] = pb[w0*128 + col];
            b[1] = pb[(w0+4)*128 + col];
            mma16(acc[0][nt], a[0], b);
            mma16(acc[1][nt], a[1], b);
        }
    }
}

// ---------------- bf16x3 mma GEMM: C[n] = act(At @ B[n] + bias) --------------
template<bool RELU>
__global__ void __launch_bounds__(256, 2) gemm_mma(
    const uint32_t* __restrict__ At, const float* __restrict__ B,
    float* __restrict__ C, const float* __restrict__ bias,
    int Kd, size_t BstrN, size_t CstrN)
{
    extern __shared__ uint32_t sm[];
    const uint32_t sBase = su32(sm);

    const int tid = threadIdx.x, lane = tid & 31, wid = tid >> 5;
    const int wm = wid & 3, wn = wid >> 2;
    const int n0 = blockIdx.x * 128;
    const int m0 = blockIdx.y * 128;
    const int nb = blockIdx.z;
    const int W3 = (Kd >> 2) * 6;
    const float* Bp = B + (size_t)nb*BstrN + n0;
    float*       Cp = C + (size_t)nb*CstrN;

    const int kb2 = (tid >> 5) * 2;
    const int bn4 = (tid & 31) * 4;

    const uint32_t aAddr0 = sBase + (uint32_t)((wm*32 + (lane & 15))*AP + (lane >> 4)*4)*4;

    float acc[2][8][4];
#pragma unroll
    for (int i = 0; i < 2; i++)
#pragma unroll
        for (int j = 0; j < 8; j++)
#pragma unroll
            for (int t = 0; t < 4; t++) acc[i][j][t] = 0.f;

    float4 rB[2][2];

    auto cpA = [&](int it){
        const int buf = it & 1;
#pragma unroll
        for (int j = 0; j < 6; j++) {
            const int ch = tid + j*256;
            const int row = ch / 12, w16 = ch - row*12;
            cpa16(sBase + (uint32_t)(buf*BUFW + row*AP + w16*4)*4,
                  At + (size_t)(m0 + row)*W3 + it*48 + w16*4);
        }
        cpcommit();
    };
    auto ldgB = [&](int it){
        const int k0 = it * 32;
#pragma unroll
        for (int q = 0; q < 2; q++) {
            const int k = k0 + kb2 + q*16;
            rB[q][0] = *(const float4*)(Bp + (size_t)k*HWP + bn4);
            rB[q][1] = *(const float4*)(Bp + (size_t)(k+1)*HWP + bn4);
        }
    };
    auto stsB = [&](int buf){
        uint32_t* bw = sm + buf*BUFW + AWBUF;
#pragma unroll
        for (int q = 0; q < 2; q++)
            storeB2x4(bw, ((tid>>5) + q*8)*3, bn4, (const float*)&rB[q][0], (const float*)&rB[q][1]);
    };

    const int nIter = Kd / 32;
    cpA(0); ldgB(0); stsB(0); cpwait<0>(); __syncthreads();
    for (int it = 0; it < nIter; ++it) {
        const int cur = it & 1;
        if (it + 1 < nIter) { cpA(it + 1); ldgB(it + 1); }
        mma_compute(aAddr0 + cur*BUFW*4, sm + cur*BUFW + AWBUF, acc, wn, lane);
        if (it + 1 < nIter) { stsB(cur ^ 1); cpwait<0>(); __syncthreads(); }
    }

    const int lq = lane >> 2, lr = lane & 3;
#pragma unroll
    for (int mt = 0; mt < 2; mt++) {
        const int r0 = m0 + wm*32 + mt*16 + lq;
        const float bv0 = __ldg(&bias[r0]);
        const float bv1 = __ldg(&bias[r0 + 8]);
#pragma unroll
        for (int nt = 0; nt < 8; nt++) {
            const int cb = n0 + wn*64 + nt*8 + 2*lr;
            float2 v0 = make_float2(acc[mt][nt][0] + bv0, acc[mt][nt][1] + bv0);
            float2 v1 = make_float2(acc[mt][nt][2] + bv1, acc[mt][nt][3] + bv1);
            if (RELU) {
                v0.x = fmaxf(v0.x, 0.f); v0.y = fmaxf(v0.y, 0.f);
                v1.x = fmaxf(v1.x, 0.f); v1.y = fmaxf(v1.y, 0.f);
            }
            *(float2*)(Cp + (size_t)r0*HWP + cb)       = v0;
            *(float2*)(Cp + (size_t)(r0 + 8)*HWP + cb) = v1;
        }
    }
}

// ---------------- dynamic 3x3 conv as implicit GEMM (bf16x3 mma) -------------
__global__ void __launch_bounds__(256, 2) conv_mma(const float* __restrict__ b_ad)
{
    extern __shared__ uint32_t sm[];
    const uint32_t sBase = su32(sm);

    const int tid = threadIdx.x, lane = tid & 31, wid = tid >> 5;
    const int wm = wid & 3, wn = wid >> 2;
    const int hw0 = blockIdx.x * 128;
    const int nb  = blockIdx.y;
    const float* fb = g_f + (size_t)nb*CM*HWP;
    const uint32_t* dwt = g_dynWT + (size_t)nb*KR*CM*192;

    const int cb2 = (tid >> 5) * 2;
    const int bn4 = (tid & 31) * 4;

    const uint32_t aAddr0 = sBase + (uint32_t)((wm*32 + (lane & 15))*AP + (lane >> 4)*4)*4;

    // 4-col group shares one spatial row (48 % 4 == 0)
    const int hwg = hw0 + bn4;
    const int oh0 = hwg / WW;
    const int ow0 = hwg - oh0*WW;

    float acc[2][8][4];
#pragma unroll
    for (int i = 0; i < 2; i++)
#pragma unroll
        for (int j = 0; j < 8; j++)
#pragma unroll
            for (int t = 0; t < 4; t++) acc[i][j][t] = 0.f;

    float rB[2][2][4];

    auto cpA = [&](int it){
        const int buf = it & 1;
        const int kk = it >> 2, c48 = (it & 3)*48;
        const uint32_t* src = dwt + (size_t)kk*CM*192;
#pragma unroll
        for (int j = 0; j < 6; j++) {
            const int ch = tid + j*256;
            const int row = ch / 12, w16 = ch - row*12;
            cpa16(sBase + (uint32_t)(buf*BUFW + row*AP + w16*4)*4,
                  src + (size_t)row*192 + c48 + w16*4);
        }
        cpcommit();
    };
    auto ldgB = [&](int it){
        const int kk = it >> 2, c0 = (it & 3) * 32;
        const int kh = kk/3 - 1, kw = kk - (kk/3)*3 - 1;
        const int hr = oh0 + kh;
        const bool rowok = (hr >= 0) && (hr < HH);
        if (kw == 0) {
            if (rowok) {
                const float* fp = fb + hr*WW + ow0;
#pragma unroll
                for (int q = 0; q < 2; q++) {
                    const int c = c0 + cb2 + q*16;
                    *(float4*)rB[q][0] = *(const float4*)(fp + (size_t)c*HWP);
                    *(float4*)rB[q][1] = *(const float4*)(fp + (size_t)(c+1)*HWP);
                }
            } else {
#pragma unroll
                for (int q = 0; q < 2; q++)
#pragma unroll
                    for (int j = 0; j < 4; j++) { rB[q][0][j] = 0.f; rB[q][1][j] = 0.f; }
            }
        } else {
            const int wc0 = ow0 + kw;
#pragma unroll
            for (int q = 0; q < 2; q++) {
                const int c = c0 + cb2 + q*16;
#pragma unroll
                for (int j = 0; j < 4; j++) {
                    const int wc = wc0 + j;
                    const bool ok = rowok && (wc >= 0) && (wc < WW);
                    const int off = ok ? (hr*WW + wc) : 0;
                    rB[q][0][j] = ok ? __ldg(fb + (size_t)c*HWP + off)     : 0.f;
                    rB[q][1][j] = ok ? __ldg(fb + (size_t)(c+1)*HWP + off) : 0.f;
                }
            }
        }
    };
    auto stsB = [&](int buf){
        uint32_t* bw = sm + buf*BUFW + AWBUF;
#pragma unroll
        for (int q = 0; q < 2; q++)
            storeB2x4(bw, ((tid>>5) + q*8)*3, bn4, rB[q][0], rB[q][1]);
    };

    const int nIter = KR * 4;   // 36
    cpA(0); ldgB(0); stsB(0); cpwait<0>(); __syncthreads();
    for (int it = 0; it < nIter; ++it) {
        const int cur = it & 1;
        if (it + 1 < nIter) { cpA(it + 1); ldgB(it + 1); }
        mma_compute(aAddr0 + cur*BUFW*4, sm + cur*BUFW + AWBUF, acc, wn, lane);
        if (it + 1 < nIter) { stsB(cur ^ 1); cpwait<0>(); __syncthreads(); }
    }

    const int lq = lane >> 2, lr = lane & 3;
    float* yb = g_y + (size_t)nb*CM*HWP;
#pragma unroll
    for (int mt = 0; mt < 2; mt++) {
        const int o0 = wm*32 + mt*16 + lq;
        const float bv0 = __ldg(&b_ad[o0]);
        const float bv1 = __ldg(&b_ad[o0 + 8]);
#pragma unroll
        for (int nt = 0; nt < 8; nt++) {
            const int cb = hw0 + wn*64 + nt*8 + 2*lr;
            float2 v0 = make_float2(acc[mt][nt][0] + bv0, acc[mt][nt][1] + bv0);
            float2 v1 = make_float2(acc[mt][nt][2] + bv1, acc[mt][nt][3] + bv1);
            *(float2*)(yb + (size_t)o0*HWP + cb)       = v0;
            *(float2*)(yb + (size_t)(o0 + 8)*HWP + cb) = v1;
        }
    }
}

// ---------------- launch -----------------------------------------------------
extern "C" void kernel_launch(void* const* d_in, const int* in_sizes, int n_in,
                              void* d_out, int out_size) {
    const float* x    = (const float*)d_in[0];
    const float* Wc   = (const float*)d_in[1];
    const float* bc   = (const float*)d_in[2];
    const float* Wkk  = (const float*)d_in[3];
    const float* bkk  = (const float*)d_in[4];
    const float* Wck  = (const float*)d_in[5];
    const float* bck  = (const float*)d_in[6];
    const float* b_ad = (const float*)d_in[7];
    const float* Wf   = (const float*)d_in[8];
    const float* bf   = (const float*)d_in[9];
    float* out = (float*)d_out;

    float* df; float* dy;
    uint32_t* dWcT; uint32_t* dWfT;
    cudaGetSymbolAddress((void**)&df,   g_f);
    cudaGetSymbolAddress((void**)&dy,   g_y);
    cudaGetSymbolAddress((void**)&dWcT, g_WcT);
    cudaGetSymbolAddress((void**)&dWfT, g_WfT);

    cudaFuncSetAttribute(gemm_mma<true>,  cudaFuncAttributeMaxDynamicSharedMemorySize, SMEM_BYTES);
    cudaFuncSetAttribute(gemm_mma<false>, cudaFuncAttributeMaxDynamicSharedMemorySize, SMEM_BYTES);
    cudaFuncSetAttribute(conv_mma,        cudaFuncAttributeMaxDynamicSharedMemorySize, SMEM_BYTES);

    // 0) one-shot weight triple-encodes
    wtrip_kernel<<<CM*(CC/4)/256, 256>>>(Wc, dWcT, CC);
    wtrip_kernel<<<PP*(CM/4)/256, 256>>>(Wf, dWfT, CM);

    // 1) mean + 3x3 max pool of x -> g_pool[n][c][12]
    pool_kernel<<<dim3(CC/16, NN), 256>>>(x);

    // 2) gk1 + sk (full-chip parallel)
    branch_kernel<<<dim3(8, NN), 256>>>(Wc, bc);

    // 3) dynW (bf16-trip layout)
    dynw_kernel<<<dim3(KR, NN), 256>>>(Wkk, bkk, Wck, bck);

    // 4) f = relu(Wc @ x + bc): M=128, K=512
    gemm_mma<true><<<dim3(HWP/128, 1, NN), 256, SMEM_BYTES>>>(
        dWcT, x, df, bc, CC, (size_t)CC*HWP, (size_t)CM*HWP);

    // 5) y = dynconv(f, dynW) + b_ad
    conv_mma<<<dim3(HWP/128, NN), 256, SMEM_BYTES>>>(b_ad);

    // 6) out = Wf @ y + bf: M=512, K=128
    gemm_mma<false><<<dim3(HWP/128, PP/128, NN), 256, SMEM_BYTES>>>(
        dWfT, dy, out, bf, CM, (size_t)CM*HWP, (size_t)PP*HWP);
}

// round 11
// speedup vs baseline: 2.4169x; 1.0123x over previous
#include <cuda_runtime.h>
#include <cuda_bf16.h>
#include <cstdint>

// Problem constants
#define NN 32
#define CC 512
#define CM 128
#define HH 48
#define WW 48
#define HWP 2304
#define PP 512
#define KR 9

// ---------------- scratch (device globals; no allocation allowed) ----------
__device__ float g_pool[NN*CC*12];   // [n][c][12]: mean, 9 region-maxes, pad
__device__ float g_gk1[NN*CM];
__device__ float g_sk[NN*CM*KR];
// bf16-triple A-layout buffers (u32 words; 6 words per 4 fp32 k-elements)
__device__ __align__(16) uint32_t g_dynWT[(size_t)NN*KR*CM*192]; // [n][kk][o][192]
__device__ __align__(16) uint32_t g_WcT[CM*768];                 // [o][768]
__device__ __align__(16) uint32_t g_WfT[PP*192];                 // [p][192]
__device__ __align__(16) float g_f[(size_t)NN*CM*HWP];           // [n][o][hw]
__device__ __align__(16) float g_y[(size_t)NN*CM*HWP];           // [n][o][hw]

// ---------------- helpers ----------------------------------------------------
__device__ __forceinline__ uint32_t su32(const void* p){
    uint32_t a; asm("{ .reg .u64 t; cvta.to.shared.u64 t, %1; cvt.u32.u64 %0, t; }"
                    : "=r"(a) : "l"(p)); return a;
}
__device__ __forceinline__ void cpa16(uint32_t d, const void* s){
    asm volatile("cp.async.cg.shared.global [%0], [%1], 16;" :: "r"(d), "l"(s));
}
__device__ __forceinline__ void cpcommit(){ asm volatile("cp.async.commit_group;" ::: "memory"); }
template<int N> __device__ __forceinline__ void cpwait(){
    asm volatile("cp.async.wait_group %0;" :: "n"(N) : "memory");
}
// bf16 m16n8k16 MMA
__device__ __forceinline__ void mma16(float* c, const uint32_t* a, const uint32_t* b){
    asm volatile("mma.sync.aligned.m16n8k16.row.col.f32.bf16.bf16.f32 "
        "{%0,%1,%2,%3}, {%4,%5,%6,%7}, {%8,%9}, {%0,%1,%2,%3};"
        : "+f"(c[0]), "+f"(c[1]), "+f"(c[2]), "+f"(c[3])
        : "r"(a[0]), "r"(a[1]), "r"(a[2]), "r"(a[3]), "r"(b[0]), "r"(b[1]));
}
// ldmatrix x4 (b16, non-transposed)
__device__ __forceinline__ void ldmA(uint32_t* a, uint32_t saddr){
    asm volatile("ldmatrix.sync.aligned.m8n8.x4.shared.b16 {%0,%1,%2,%3}, [%4];"
      : "=r"(a[0]), "=r"(a[1]), "=r"(a[2]), "=r"(a[3]) : "r"(saddr));
}
// 2-term bf16 split: f = hi + lo (+ O(2^-17 f))
__device__ __forceinline__ void bsplit(float f, uint16_t& h, uint16_t& l){
    __nv_bfloat16 bh = __float2bfloat16(f);
    float r = f - __bfloat162float(bh);
    __nv_bfloat16 bl = __float2bfloat16(r);
    h = __bfloat16_as_ushort(bh);
    l = __bfloat16_as_ushort(bl);
}
__device__ __forceinline__ uint32_t pk(uint16_t a, uint16_t b){
    return (uint32_t)a | ((uint32_t)b << 16);
}
// A triple encode: 4 consecutive fp32 k -> 6 u32 words
__device__ __forceinline__ void storeA4(uint32_t* dst, float4 v){
    uint16_t h0,l0,h1,l1,h2,l2,h3,l3;
    bsplit(v.x, h0, l0); bsplit(v.y, h1, l1);
    bsplit(v.z, h2, l2); bsplit(v.w, h3, l3);
    *(uint2*)(dst)     = make_uint2(pk(h0,l0), pk(h0,h1));
    *(uint2*)(dst + 2) = make_uint2(pk(l1,h1), pk(h2,l2));
    *(uint2*)(dst + 4) = make_uint2(pk(h2,h3), pk(l3,h3));
}
// B triple encode: two consecutive fp32 k rows (k even), 4 cols -> 3 swizzled uint4
__device__ __forceinline__ void storeB2x4(uint32_t* bw, int wp, int bn4,
                                          const float* r0, const float* r1){
    uint32_t w0[4], w1[4], w2[4];
#pragma unroll
    for (int j = 0; j < 4; j++) {
        uint16_t H0,L0,H1,L1;
        bsplit(r0[j], H0, L0);
        bsplit(r1[j], H1, L1);
        w0[j] = pk(H0,H0); w1[j] = pk(L0,H1); w2[j] = pk(H1,L1);
    }
    *(uint4*)(bw + (wp  )*128 + (bn4 ^ (((wp  )&3)<<3))) = make_uint4(w0[0],w0[1],w0[2],w0[3]);
    *(uint4*)(bw + (wp+1)*128 + (bn4 ^ (((wp+1)&3)<<3))) = make_uint4(w1[0],w1[1],w1[2],w1[3]);
    *(uint4*)(bw + (wp+2)*128 + (bn4 ^ (((wp+2)&3)<<3))) = make_uint4(w2[0],w2[1],w2[2],w2[3]);
}

// smem geometry (u32 units). A: [128 rows][48 words + pad->52]; B: [48 words][128 cols]
#define AP 52
#define AWBUF (128*AP)          // 6656
#define BWBUF (48*128)          // 6144
#define BUFW  (AWBUF + BWBUF)   // 12800
#define SMEM_BYTES (2*BUFW*4)   // 102400

// conv halo-B geometry: [48 words][200 cols] (4 rows x 50 w, padded edges)
#define CPW 200
#define CBWORDS (48*CPW)                       // 9600 u32
#define CONV_SMEM ((2*AWBUF + CBWORDS)*4)      // 91648 B

// ---------------- kernel 1: mean + 3x3 adaptive max pool (coalesced) -------
__global__ void pool_kernel(const float* __restrict__ x) {
    const int g = threadIdx.x >> 4, l = threadIdx.x & 15;
    const int c = blockIdx.x*16 + g, n = blockIdx.y;
    const float4* xp = (const float4*)(x + (size_t)(n*CC + c)*HWP);

    float s = 0.f;
    float mx[KR];
#pragma unroll
    for (int r = 0; r < KR; r++) {
        const int hb = r/3, wb = r - (r/3)*3;
        float mr = -3.402823466e38f;
#pragma unroll
        for (int j = 0; j < 4; j++) {
            int idx = j*16 + l;
            int row = idx >> 2, w4 = idx & 3;
            float4 v = xp[(hb*16 + row)*12 + wb*4 + w4];
            s += v.x + v.y + v.z + v.w;
            mr = fmaxf(mr, fmaxf(fmaxf(v.x, v.y), fmaxf(v.z, v.w)));
        }
        mx[r] = mr;
    }
#pragma unroll
    for (int o = 8; o > 0; o >>= 1) {
        s += __shfl_down_sync(0xffffffffu, s, o, 16);
#pragma unroll
        for (int r = 0; r < KR; r++)
            mx[r] = fmaxf(mx[r], __shfl_down_sync(0xffffffffu, mx[r], o, 16));
    }
    if (l == 0) {
        float* dst = g_pool + (size_t)(n*CC + c)*12;
        dst[0] = s * (1.0f/(float)HWP);
#pragma unroll
        for (int r = 0; r < KR; r++) dst[1+r] = mx[r];
        dst[10] = 0.f; dst[11] = 0.f;
    }
}

// ---------------- kernel 2: branches (full-chip parallel) -------------------
__global__ void __launch_bounds__(256) branch_kernel(
    const float* __restrict__ Wc, const float* __restrict__ bc) {
    const int og = blockIdx.x, n = blockIdx.y;
    const int lane = threadIdx.x & 31, w = threadIdx.x >> 5;
    const int o0 = og*16 + w*2;
    const int o1 = o0 + 1;

    const float* pb = g_pool + (size_t)n*CC*12;
    const float* wr0 = Wc + (size_t)o0*CC;
    const float* wr1 = Wc + (size_t)o1*CC;

    float a0[10], a1[10];
#pragma unroll
    for (int j = 0; j < 10; j++) { a0[j] = 0.f; a1[j] = 0.f; }

#pragma unroll
    for (int i = 0; i < 16; i++) {
        const int c = lane + i*32;
        const float wv0 = __ldg(&wr0[c]);
        const float wv1 = __ldg(&wr1[c]);
        const float4* pc = (const float4*)(pb + c*12);
        float4 p0 = __ldg(pc), p1 = __ldg(pc+1), p2 = __ldg(pc+2);
        a0[0] += wv0*p0.x; a0[1] += wv0*p0.y; a0[2] += wv0*p0.z; a0[3] += wv0*p0.w;
        a0[4] += wv0*p1.x; a0[5] += wv0*p1.y; a0[6] += wv0*p1.z; a0[7] += wv0*p1.w;
        a0[8] += wv0*p2.x; a0[9] += wv0*p2.y;
        a1[0] += wv1*p0.x; a1[1] += wv1*p0.y; a1[2] += wv1*p0.z; a1[3] += wv1*p0.w;
        a1[4] += wv1*p1.x; a1[5] += wv1*p1.y; a1[6] += wv1*p1.z; a1[7] += wv1*p1.w;
        a1[8] += wv1*p2.x; a1[9] += wv1*p2.y;
    }
#pragma unroll
    for (int off = 16; off > 0; off >>= 1)
#pragma unroll
        for (int j = 0; j < 10; j++) {
            a0[j] += __shfl_down_sync(0xffffffffu, a0[j], off);
            a1[j] += __shfl_down_sync(0xffffffffu, a1[j], off);
        }
    if (lane == 0) {
        const float bv0 = bc[o0], bv1 = bc[o1];
        g_gk1[n*CM + o0] = fmaxf(a0[0] + bv0, 0.f);
        g_gk1[n*CM + o1] = fmaxf(a1[0] + bv1, 0.f);
#pragma unroll
        for (int r = 0; r < KR; r++) {
            g_sk[(size_t)(n*CM + o0)*KR + r] = fmaxf(a0[1+r] + bv0, 0.f);
            g_sk[(size_t)(n*CM + o1)*KR + r] = fmaxf(a1[1+r] + bv1, 0.f);
        }
    }
}

// ---------------- weight triple-encode (one-shot, tiny) ---------------------
__global__ void wtrip_kernel(const float* __restrict__ W, uint32_t* __restrict__ T, int Kd) {
    const int idx = blockIdx.x*256 + threadIdx.x;
    const int gpr = Kd >> 2;
    const int row = idx / gpr, g = idx - row*gpr;
    float4 v = *(const float4*)(W + (size_t)row*Kd + 4*g);
    storeA4(T + (size_t)row*(gpr*6) + 6*g, v);
}

// ---------------- kernel 3: dynamic weights, emitted in trip layout ---------
__global__ void dynw_kernel(const float* __restrict__ Wkk, const float* __restrict__ bkk,
                            const float* __restrict__ Wck, const float* __restrict__ bck) {
    int r = blockIdx.x, n = blockIdx.y;
    int tid = threadIdx.x;
    __shared__ float s_gk[CM], s_sk[CM];
    if (tid < CM) {
        float gk1 = g_gk1[n*CM + tid];
        s_gk[tid] = gk1 * Wkk[r] + bkk[r];
        s_sk[tid] = g_sk[(size_t)(n*CM + tid)*KR + r];
    }
    __syncthreads();
    uint32_t* dst = g_dynWT + (size_t)(n*KR + r)*CM*192;
#pragma unroll
    for (int i = 0; i < 16; i++) {
        const int idx = tid + i*256;
        const int o = idx >> 5, gc = idx & 31;
        const int c4 = gc*4;
        const float wa = Wck[o*2], wb = Wck[o*2+1], bo = bck[o];
        float4 v;
        v.x = fmaxf(wa*s_gk[c4]   + wb*s_sk[c4]   + bo, 0.f);
        v.y = fmaxf(wa*s_gk[c4+1] + wb*s_sk[c4+1] + bo, 0.f);
        v.z = fmaxf(wa*s_gk[c4+2] + wb*s_sk[c4+2] + bo, 0.f);
        v.w = fmaxf(wa*s_gk[c4+3] + wb*s_sk[c4+3] + bo, 0.f);
        storeA4(dst + (size_t)o*192 + gc*6, v);
    }
}

// ---------------- shared bf16 mma compute (ldmatrix A + LDS B) --------------
__device__ __forceinline__ void mma_compute(
    uint32_t aAddr, const uint32_t* pb, float acc[2][8][4],
    int wn, int lane)
{
    const int lq = lane >> 2, lr = lane & 3;
#pragma unroll
    for (int s = 0; s < 6; s++) {
        uint32_t a[2][4];
        ldmA(a[0], aAddr + s*32);
        ldmA(a[1], aAddr + 16*AP*4 + s*32);
        const int w0 = s*8 + lr;
        const int xr = (w0 & 3) << 3;
        const int nb = wn*64 + lq;
#pragma unroll
        for (int nt = 0; nt < 8; nt++) {
            const int col = (nb + nt*8) ^ xr;
            uint32_t b[2];
            b[0] = pb[w0*128 + col];
            b[1] = pb[(w0+4)*128 + col];
            mma16(acc[0][nt], a[0], b);
            mma16(acc[1][nt], a[1], b);
        }
    }
}

// ---------------- bf16x3 mma GEMM: C[n] = act(At @ B[n] + bias) --------------
template<bool RELU>
__global__ void __launch_bounds__(256, 2) gemm_mma(
    const uint32_t* __restrict__ At, const float* __restrict__ B,
    float* __restrict__ C, const float* __restrict__ bias,
    int Kd, size_t BstrN, size_t CstrN)
{
    extern __shared__ uint32_t sm[];
    const uint32_t sBase = su32(sm);

    const int tid = threadIdx.x, lane = tid & 31, wid = tid >> 5;
    const int wm = wid & 3, wn = wid >> 2;
    const int n0 = blockIdx.x * 128;
    const int m0 = blockIdx.y * 128;
    const int nb = blockIdx.z;
    const int W3 = (Kd >> 2) * 6;
    const float* Bp = B + (size_t)nb*BstrN + n0;
    float*       Cp = C + (size_t)nb*CstrN;

    const int kb2 = (tid >> 5) * 2;
    const int bn4 = (tid & 31) * 4;

    const uint32_t aAddr0 = sBase + (uint32_t)((wm*32 + (lane & 15))*AP + (lane >> 4)*4)*4;

    float acc[2][8][4];
#pragma unroll
    for (int i = 0; i < 2; i++)
#pragma unroll
        for (int j = 0; j < 8; j++)
#pragma unroll
            for (int t = 0; t < 4; t++) acc[i][j][t] = 0.f;

    float4 rB[2][2];

    auto cpA = [&](int it){
        const int buf = it & 1;
#pragma unroll
        for (int j = 0; j < 6; j++) {
            const int ch = tid + j*256;
            const int row = ch / 12, w16 = ch - row*12;
            cpa16(sBase + (uint32_t)(buf*BUFW + row*AP + w16*4)*4,
                  At + (size_t)(m0 + row)*W3 + it*48 + w16*4);
        }
        cpcommit();
    };
    auto ldgB = [&](int it){
        const int k0 = it * 32;
#pragma unroll
        for (int q = 0; q < 2; q++) {
            const int k = k0 + kb2 + q*16;
            rB[q][0] = *(const float4*)(Bp + (size_t)k*HWP + bn4);
            rB[q][1] = *(const float4*)(Bp + (size_t)(k+1)*HWP + bn4);
        }
    };
    auto stsB = [&](int buf){
        uint32_t* bw = sm + buf*BUFW + AWBUF;
#pragma unroll
        for (int q = 0; q < 2; q++)
            storeB2x4(bw, ((tid>>5) + q*8)*3, bn4, (const float*)&rB[q][0], (const float*)&rB[q][1]);
    };

    const int nIter = Kd / 32;
    cpA(0); ldgB(0); stsB(0); cpwait<0>(); __syncthreads();
    for (int it = 0; it < nIter; ++it) {
        const int cur = it & 1;
        if (it + 1 < nIter) { cpA(it + 1); ldgB(it + 1); }
        mma_compute(aAddr0 + cur*BUFW*4, sm + cur*BUFW + AWBUF, acc, wn, lane);
        if (it + 1 < nIter) { stsB(cur ^ 1); cpwait<0>(); __syncthreads(); }
    }

    const int lq = lane >> 2, lr = lane & 3;
#pragma unroll
    for (int mt = 0; mt < 2; mt++) {
        const int r0 = m0 + wm*32 + mt*16 + lq;
        const float bv0 = __ldg(&bias[r0]);
        const float bv1 = __ldg(&bias[r0 + 8]);
#pragma unroll
        for (int nt = 0; nt < 8; nt++) {
            const int cb = n0 + wn*64 + nt*8 + 2*lr;
            float2 v0 = make_float2(acc[mt][nt][0] + bv0, acc[mt][nt][1] + bv0);
            float2 v1 = make_float2(acc[mt][nt][2] + bv1, acc[mt][nt][3] + bv1);
            if (RELU) {
                v0.x = fmaxf(v0.x, 0.f); v0.y = fmaxf(v0.y, 0.f);
                v1.x = fmaxf(v1.x, 0.f); v1.y = fmaxf(v1.y, 0.f);
            }
            *(float2*)(Cp + (size_t)r0*HWP + cb)       = v0;
            *(float2*)(Cp + (size_t)(r0 + 8)*HWP + cb) = v1;
        }
    }
}

// ---------------- conv: halo-tiled implicit GEMM (bf16x3 mma) ----------------
// Block output: 128 o x 96 hw (2 full image rows h0, h0+1).
// B smem: trip f tile [48 words][4 rows x 50 w] loaded once per 32-c chunk;
// 9 taps read it at col offset kh*50+kw; w=+-1 edges & OOB rows are zeros.
__global__ void __launch_bounds__(256, 2) conv_mma(const float* __restrict__ b_ad)
{
    extern __shared__ uint32_t sm[];
    const uint32_t sBase = su32(sm);
    uint32_t* bw = sm + 2*AWBUF;

    const int tid = threadIdx.x, lane = tid & 31, wid = tid >> 5;
    const int wm = wid & 3, wn = wid >> 2;   // wm: 32-o rows; wn: 48-hw cols
    const int bx = blockIdx.x;               // 24 tiles of 2 rows
    const int h0 = bx*2;
    const int hw0 = bx*96;
    const int nb  = blockIdx.y;
    const float* fb = g_f + (size_t)nb*CM*HWP;
    const uint32_t* dwt = g_dynWT + (size_t)nb*KR*CM*192;

    const uint32_t aAddr0 = sBase + (uint32_t)((wm*32 + (lane & 15))*AP + (lane >> 4)*4)*4;

    // zero the 8 pad columns (w=-1, w=48 per input row) for all 48 k-words
    for (int i = tid; i < 48*8; i += 256) {
        const int row = i >> 3, e = i & 7;
        const int r = e >> 1, side = e & 1;
        bw[row*CPW + r*50 + (side ? 49 : 0)] = 0;
    }

    float acc[2][6][4];
#pragma unroll
    for (int i = 0; i < 2; i++)
#pragma unroll
        for (int j = 0; j < 6; j++)
#pragma unroll
            for (int t = 0; t < 4; t++) acc[i][j][t] = 0.f;

    auto cpA = [&](int it){                 // it = chunk*9 + kk
        const int buf = it & 1;
        const int kk = it % 9, c48 = (it/9)*48;
        const uint32_t* src = dwt + (size_t)kk*CM*192;
#pragma unroll
        for (int j = 0; j < 6; j++) {
            const int ch = tid + j*256;
            const int row = ch / 12, w16 = ch - row*12;
            cpa16(sBase + (uint32_t)(buf*AWBUF + row*AP + w16*4)*4,
                  src + (size_t)row*192 + c48 + w16*4);
        }
        cpcommit();
    };

    auto loadB = [&](int chunk){
        const int c0 = chunk*32;
#pragma unroll
        for (int j = 0; j < 12; j++) {
            const int slot = tid + j*256;        // 0..3071 = 16 pairs x 192 pos
            const int p = slot / 192, pos = slot - p*192;
            const int r = pos / 48, w = pos - r*48;
            const int hin = h0 - 1 + r;
            const bool ok = (hin >= 0) && (hin < HH);
            float v0 = 0.f, v1 = 0.f;
            if (ok) {
                const float* fp = fb + (size_t)(c0 + 2*p)*HWP + hin*WW + w;
                v0 = __ldg(fp);
                v1 = __ldg(fp + HWP);
            }
            uint16_t H0,L0,H1,L1;
            bsplit(v0, H0, L0); bsplit(v1, H1, L1);
            uint32_t* q = bw + (3*p)*CPW + r*50 + 1 + w;
            q[0]     = pk(H0,H0);
            q[CPW]   = pk(L0,H1);
            q[2*CPW] = pk(H1,L1);
        }
    };

    const int lq = lane >> 2, lr = lane & 3;
    const int colb = (wn + 1)*50 + 1 + lq;   // fragment col base (tap 0 center)

    auto mmaStep = [&](int buf, int tapoff){
        const uint32_t aAddr = aAddr0 + (uint32_t)(buf*AWBUF)*4;
#pragma unroll
        for (int s = 0; s < 6; s++) {
            uint32_t a[2][4];
            ldmA(a[0], aAddr + s*32);
            ldmA(a[1], aAddr + 16*AP*4 + s*32);
            const uint32_t* pb0 = bw + (s*8 + lr)*CPW + tapoff;
#pragma unroll
            for (int nt = 0; nt < 6; nt++) {
                const int col = colb + nt*8;
                uint32_t b[2];
                b[0] = pb0[col];
                b[1] = pb0[4*CPW + col];
                mma16(acc[0][nt], a[0], b);
                mma16(acc[1][nt], a[1], b);
            }
        }
    };

    cpA(0); cpwait<0>();
    for (int chunk = 0; chunk < 4; chunk++) {
        __syncthreads();                 // prior readers done / zeros+A visible
        loadB(chunk);
        __syncthreads();
#pragma unroll
        for (int kk = 0; kk < KR; kk++) {
            const int it = chunk*9 + kk;
            if (it + 1 < 36) cpA(it + 1);
            const int kh = kk/3 - 1, kw = kk - (kk/3)*3 - 1;
            mmaStep(it & 1, kh*50 + kw);
            if (it + 1 < 36) { cpwait<0>(); __syncthreads(); }
        }
    }

    // epilogue: y[o][hw0 + wn*48 + nt*8 + 2lr + {0,1}]
    float* yb = g_y + (size_t)nb*CM*HWP;
#pragma unroll
    for (int mt = 0; mt < 2; mt++) {
        const int o0 = wm*32 + mt*16 + lq;
        const float bv0 = __ldg(&b_ad[o0]);
        const float bv1 = __ldg(&b_ad[o0 + 8]);
#pragma unroll
        for (int nt = 0; nt < 6; nt++) {
            const int cb = hw0 + wn*48 + nt*8 + 2*lr;
            float2 v0 = make_float2(acc[mt][nt][0] + bv0, acc[mt][nt][1] + bv0);
            float2 v1 = make_float2(acc[mt][nt][2] + bv1, acc[mt][nt][3] + bv1);
            *(float2*)(yb + (size_t)o0*HWP + cb)       = v0;
            *(float2*)(yb + (size_t)(o0 + 8)*HWP + cb) = v1;
        }
    }
}

// ---------------- launch -----------------------------------------------------
extern "C" void kernel_launch(void* const* d_in, const int* in_sizes, int n_in,
                              void* d_out, int out_size) {
    const float* x    = (const float*)d_in[0];
    const float* Wc   = (const float*)d_in[1];
    const float* bc   = (const float*)d_in[2];
    const float* Wkk  = (const float*)d_in[3];
    const float* bkk  = (const float*)d_in[4];
    const float* Wck  = (const float*)d_in[5];
    const float* bck  = (const float*)d_in[6];
    const float* b_ad = (const float*)d_in[7];
    const float* Wf   = (const float*)d_in[8];
    const float* bf   = (const float*)d_in[9];
    float* out = (float*)d_out;

    float* df; float* dy;
    uint32_t* dWcT; uint32_t* dWfT;
    cudaGetSymbolAddress((void**)&df,   g_f);
    cudaGetSymbolAddress((void**)&dy,   g_y);
    cudaGetSymbolAddress((void**)&dWcT, g_WcT);
    cudaGetSymbolAddress((void**)&dWfT, g_WfT);

    cudaFuncSetAttribute(gemm_mma<true>,  cudaFuncAttributeMaxDynamicSharedMemorySize, SMEM_BYTES);
    cudaFuncSetAttribute(gemm_mma<false>, cudaFuncAttributeMaxDynamicSharedMemorySize, SMEM_BYTES);
    cudaFuncSetAttribute(conv_mma,        cudaFuncAttributeMaxDynamicSharedMemorySize, CONV_SMEM);

    // 0) one-shot weight triple-encodes
    wtrip_kernel<<<CM*(CC/4)/256, 256>>>(Wc, dWcT, CC);
    wtrip_kernel<<<PP*(CM/4)/256, 256>>>(Wf, dWfT, CM);

    // 1) mean + 3x3 max pool of x -> g_pool[n][c][12]
    pool_kernel<<<dim3(CC/16, NN), 256>>>(x);

    // 2) gk1 + sk (full-chip parallel)
    branch_kernel<<<dim3(8, NN), 256>>>(Wc, bc);

    // 3) dynW (bf16-trip layout)
    dynw_kernel<<<dim3(KR, NN), 256>>>(Wkk, bkk, Wck, bck);

    // 4) f = relu(Wc @ x + bc): M=128, K=512
    gemm_mma<true><<<dim3(HWP/128, 1, NN), 256, SMEM_BYTES>>>(
        dWcT, x, df, bc, CC, (size_t)CC*HWP, (size_t)CM*HWP);

    // 5) y = dynconv(f, dynW) + b_ad  (halo-tiled: 24 two-row tiles)
    conv_mma<<<dim3(24, NN), 256, CONV_SMEM>>>(b_ad);

    // 6) out = Wf @ y + bf: M=512, K=128
    gemm_mma<false><<<dim3(HWP/128, PP/128, NN), 256, SMEM_BYTES>>>(
        dWfT, dy, out, bf, CM, (size_t)CM*HWP, (size_t)PP*HWP);
}

// round 12
// speedup vs baseline: 2.4254x; 1.0035x over previous
#include <cuda_runtime.h>
#include <cuda_bf16.h>
#include <cstdint>

// Problem constants
#define NN 32
#define CC 512
#define CM 128
#define HH 48
#define WW 48
#define HWP 2304
#define PP 512
#define KR 9

// ---------------- scratch (device globals; no allocation allowed) ----------
__device__ float g_pool[NN*CC*12];   // [n][c][12]: mean, 9 region-maxes, pad
__device__ float g_gk1[NN*CM];
__device__ float g_sk[NN*CM*KR];
// bf16-triple A-layout buffers (u32 words; 6 words per 4 fp32 k-elements)
__device__ __align__(16) uint32_t g_dynWT[(size_t)NN*KR*CM*192]; // [n][kk][o][192]
__device__ __align__(16) uint32_t g_WcT[CM*768];                 // [o][768]
__device__ __align__(16) uint32_t g_WfT[PP*192];                 // [p][192]
__device__ __align__(16) float g_f[(size_t)NN*CM*HWP];           // [n][o][hw]
__device__ __align__(16) float g_y[(size_t)NN*CM*HWP];           // [n][o][hw]

// ---------------- helpers ----------------------------------------------------
__device__ __forceinline__ uint32_t su32(const void* p){
    uint32_t a; asm("{ .reg .u64 t; cvta.to.shared.u64 t, %1; cvt.u32.u64 %0, t; }"
                    : "=r"(a) : "l"(p)); return a;
}
__device__ __forceinline__ void cpa16(uint32_t d, const void* s){
    asm volatile("cp.async.cg.shared.global [%0], [%1], 16;" :: "r"(d), "l"(s));
}
__device__ __forceinline__ void cpcommit(){ asm volatile("cp.async.commit_group;" ::: "memory"); }
template<int N> __device__ __forceinline__ void cpwait(){
    asm volatile("cp.async.wait_group %0;" :: "n"(N) : "memory");
}
// bf16 m16n8k16 MMA
__device__ __forceinline__ void mma16(float* c, const uint32_t* a, const uint32_t* b){
    asm volatile("mma.sync.aligned.m16n8k16.row.col.f32.bf16.bf16.f32 "
        "{%0,%1,%2,%3}, {%4,%5,%6,%7}, {%8,%9}, {%0,%1,%2,%3};"
        : "+f"(c[0]), "+f"(c[1]), "+f"(c[2]), "+f"(c[3])
        : "r"(a[0]), "r"(a[1]), "r"(a[2]), "r"(a[3]), "r"(b[0]), "r"(b[1]));
}
// ldmatrix x4 (b16, non-transposed)
__device__ __forceinline__ void ldmA(uint32_t* a, uint32_t saddr){
    asm volatile("ldmatrix.sync.aligned.m8n8.x4.shared.b16 {%0,%1,%2,%3}, [%4];"
      : "=r"(a[0]), "=r"(a[1]), "=r"(a[2]), "=r"(a[3]) : "r"(saddr));
}
// 2-term bf16 split: f = hi + lo (+ O(2^-17 f))
__device__ __forceinline__ void bsplit(float f, uint16_t& h, uint16_t& l){
    __nv_bfloat16 bh = __float2bfloat16(f);
    float r = f - __bfloat162float(bh);
    __nv_bfloat16 bl = __float2bfloat16(r);
    h = __bfloat16_as_ushort(bh);
    l = __bfloat16_as_ushort(bl);
}
__device__ __forceinline__ uint32_t pk(uint16_t a, uint16_t b){
    return (uint32_t)a | ((uint32_t)b << 16);
}
// A triple encode: 4 consecutive fp32 k -> 6 u32 words
__device__ __forceinline__ void storeA4(uint32_t* dst, float4 v){
    uint16_t h0,l0,h1,l1,h2,l2,h3,l3;
    bsplit(v.x, h0, l0); bsplit(v.y, h1, l1);
    bsplit(v.z, h2, l2); bsplit(v.w, h3, l3);
    *(uint2*)(dst)     = make_uint2(pk(h0,l0), pk(h0,h1));
    *(uint2*)(dst + 2) = make_uint2(pk(l1,h1), pk(h2,l2));
    *(uint2*)(dst + 4) = make_uint2(pk(h2,h3), pk(l3,h3));
}
// B triple encode: two consecutive fp32 k rows (k even), 4 cols -> 3 swizzled uint4
__device__ __forceinline__ void storeB2x4(uint32_t* bw, int wp, int bn4,
                                          const float* r0, const float* r1){
    uint32_t w0[4], w1[4], w2[4];
#pragma unroll
    for (int j = 0; j < 4; j++) {
        uint16_t H0,L0,H1,L1;
        bsplit(r0[j], H0, L0);
        bsplit(r1[j], H1, L1);
        w0[j] = pk(H0,H0); w1[j] = pk(L0,H1); w2[j] = pk(H1,L1);
    }
    *(uint4*)(bw + (wp  )*128 + (bn4 ^ (((wp  )&3)<<3))) = make_uint4(w0[0],w0[1],w0[2],w0[3]);
    *(uint4*)(bw + (wp+1)*128 + (bn4 ^ (((wp+1)&3)<<3))) = make_uint4(w1[0],w1[1],w1[2],w1[3]);
    *(uint4*)(bw + (wp+2)*128 + (bn4 ^ (((wp+2)&3)<<3))) = make_uint4(w2[0],w2[1],w2[2],w2[3]);
}

// smem geometry (u32 units). A: [128 rows][48 words + pad->52]; B: [48 words][128 cols]
#define AP 52
#define AWBUF (128*AP)          // 6656
#define BWBUF (48*128)          // 6144
#define BUFW  (AWBUF + BWBUF)   // 12800
#define SMEM_BYTES (2*BUFW*4)   // 102400

// conv halo-B geometry: [48 words][200 cols] (4 rows x 50 w, padded edges)
#define CPW 200
#define CBWORDS (48*CPW)                       // 9600 u32
#define CONV_SMEM ((2*AWBUF + CBWORDS)*4)      // 91648 B

// ---------------- kernel 1: mean + 3x3 adaptive max pool (coalesced) -------
__global__ void pool_kernel(const float* __restrict__ x) {
    const int g = threadIdx.x >> 4, l = threadIdx.x & 15;
    const int c = blockIdx.x*16 + g, n = blockIdx.y;
    const float4* xp = (const float4*)(x + (size_t)(n*CC + c)*HWP);

    float s = 0.f;
    float mx[KR];
#pragma unroll
    for (int r = 0; r < KR; r++) {
        const int hb = r/3, wb = r - (r/3)*3;
        float mr = -3.402823466e38f;
#pragma unroll
        for (int j = 0; j < 4; j++) {
            int idx = j*16 + l;
            int row = idx >> 2, w4 = idx & 3;
            float4 v = xp[(hb*16 + row)*12 + wb*4 + w4];
            s += v.x + v.y + v.z + v.w;
            mr = fmaxf(mr, fmaxf(fmaxf(v.x, v.y), fmaxf(v.z, v.w)));
        }
        mx[r] = mr;
    }
#pragma unroll
    for (int o = 8; o > 0; o >>= 1) {
        s += __shfl_down_sync(0xffffffffu, s, o, 16);
#pragma unroll
        for (int r = 0; r < KR; r++)
            mx[r] = fmaxf(mx[r], __shfl_down_sync(0xffffffffu, mx[r], o, 16));
    }
    if (l == 0) {
        float* dst = g_pool + (size_t)(n*CC + c)*12;
        dst[0] = s * (1.0f/(float)HWP);
#pragma unroll
        for (int r = 0; r < KR; r++) dst[1+r] = mx[r];
        dst[10] = 0.f; dst[11] = 0.f;
    }
}

// ---------------- kernel 2: branches (full-chip parallel) -------------------
__global__ void __launch_bounds__(256) branch_kernel(
    const float* __restrict__ Wc, const float* __restrict__ bc) {
    const int og = blockIdx.x, n = blockIdx.y;
    const int lane = threadIdx.x & 31, w = threadIdx.x >> 5;
    const int o0 = og*16 + w*2;
    const int o1 = o0 + 1;

    const float* pb = g_pool + (size_t)n*CC*12;
    const float* wr0 = Wc + (size_t)o0*CC;
    const float* wr1 = Wc + (size_t)o1*CC;

    float a0[10], a1[10];
#pragma unroll
    for (int j = 0; j < 10; j++) { a0[j] = 0.f; a1[j] = 0.f; }

#pragma unroll
    for (int i = 0; i < 16; i++) {
        const int c = lane + i*32;
        const float wv0 = __ldg(&wr0[c]);
        const float wv1 = __ldg(&wr1[c]);
        const float4* pc = (const float4*)(pb + c*12);
        float4 p0 = __ldg(pc), p1 = __ldg(pc+1), p2 = __ldg(pc+2);
        a0[0] += wv0*p0.x; a0[1] += wv0*p0.y; a0[2] += wv0*p0.z; a0[3] += wv0*p0.w;
        a0[4] += wv0*p1.x; a0[5] += wv0*p1.y; a0[6] += wv0*p1.z; a0[7] += wv0*p1.w;
        a0[8] += wv0*p2.x; a0[9] += wv0*p2.y;
        a1[0] += wv1*p0.x; a1[1] += wv1*p0.y; a1[2] += wv1*p0.z; a1[3] += wv1*p0.w;
        a1[4] += wv1*p1.x; a1[5] += wv1*p1.y; a1[6] += wv1*p1.z; a1[7] += wv1*p1.w;
        a1[8] += wv1*p2.x; a1[9] += wv1*p2.y;
    }
#pragma unroll
    for (int off = 16; off > 0; off >>= 1)
#pragma unroll
        for (int j = 0; j < 10; j++) {
            a0[j] += __shfl_down_sync(0xffffffffu, a0[j], off);
            a1[j] += __shfl_down_sync(0xffffffffu, a1[j], off);
        }
    if (lane == 0) {
        const float bv0 = bc[o0], bv1 = bc[o1];
        g_gk1[n*CM + o0] = fmaxf(a0[0] + bv0, 0.f);
        g_gk1[n*CM + o1] = fmaxf(a1[0] + bv1, 0.f);
#pragma unroll
        for (int r = 0; r < KR; r++) {
            g_sk[(size_t)(n*CM + o0)*KR + r] = fmaxf(a0[1+r] + bv0, 0.f);
            g_sk[(size_t)(n*CM + o1)*KR + r] = fmaxf(a1[1+r] + bv1, 0.f);
        }
    }
}

// ---------------- weight triple-encode (one-shot, tiny) ---------------------
__global__ void wtrip_kernel(const float* __restrict__ W, uint32_t* __restrict__ T, int Kd) {
    const int idx = blockIdx.x*256 + threadIdx.x;
    const int gpr = Kd >> 2;
    const int row = idx / gpr, g = idx - row*gpr;
    float4 v = *(const float4*)(W + (size_t)row*Kd + 4*g);
    storeA4(T + (size_t)row*(gpr*6) + 6*g, v);
}

// ---------------- kernel 3: dynamic weights, emitted in trip layout ---------
__global__ void dynw_kernel(const float* __restrict__ Wkk, const float* __restrict__ bkk,
                            const float* __restrict__ Wck, const float* __restrict__ bck) {
    int r = blockIdx.x, n = blockIdx.y;
    int tid = threadIdx.x;
    __shared__ float s_gk[CM], s_sk[CM];
    if (tid < CM) {
        float gk1 = g_gk1[n*CM + tid];
        s_gk[tid] = gk1 * Wkk[r] + bkk[r];
        s_sk[tid] = g_sk[(size_t)(n*CM + tid)*KR + r];
    }
    __syncthreads();
    uint32_t* dst = g_dynWT + (size_t)(n*KR + r)*CM*192;
#pragma unroll
    for (int i = 0; i < 16; i++) {
        const int idx = tid + i*256;
        const int o = idx >> 5, gc = idx & 31;
        const int c4 = gc*4;
        const float wa = Wck[o*2], wb = Wck[o*2+1], bo = bck[o];
        float4 v;
        v.x = fmaxf(wa*s_gk[c4]   + wb*s_sk[c4]   + bo, 0.f);
        v.y = fmaxf(wa*s_gk[c4+1] + wb*s_sk[c4+1] + bo, 0.f);
        v.z = fmaxf(wa*s_gk[c4+2] + wb*s_sk[c4+2] + bo, 0.f);
        v.w = fmaxf(wa*s_gk[c4+3] + wb*s_sk[c4+3] + bo, 0.f);
        storeA4(dst + (size_t)o*192 + gc*6, v);
    }
}

// ---------------- shared bf16 mma compute (ldmatrix A + LDS B) --------------
__device__ __forceinline__ void mma_compute(
    uint32_t aAddr, const uint32_t* pb, float acc[2][8][4],
    int wn, int lane)
{
    const int lq = lane >> 2, lr = lane & 3;
#pragma unroll
    for (int s = 0; s < 6; s++) {
        uint32_t a[2][4];
        ldmA(a[0], aAddr + s*32);
        ldmA(a[1], aAddr + 16*AP*4 + s*32);
        const int w0 = s*8 + lr;
        const int xr = (w0 & 3) << 3;
        const int nb = wn*64 + lq;
#pragma unroll
        for (int nt = 0; nt < 8; nt++) {
            const int col = (nb + nt*8) ^ xr;
            uint32_t b[2];
            b[0] = pb[w0*128 + col];
            b[1] = pb[(w0+4)*128 + col];
            mma16(acc[0][nt], a[0], b);
            mma16(acc[1][nt], a[1], b);
        }
    }
}

// ---------------- bf16x3 mma GEMM: C[n] = act(At @ B[n] + bias) --------------
template<bool RELU>
__global__ void __launch_bounds__(256, 2) gemm_mma(
    const uint32_t* __restrict__ At, const float* __restrict__ B,
    float* __restrict__ C, const float* __restrict__ bias,
    int Kd, size_t BstrN, size_t CstrN)
{
    extern __shared__ uint32_t sm[];
    const uint32_t sBase = su32(sm);

    const int tid = threadIdx.x, lane = tid & 31, wid = tid >> 5;
    const int wm = wid & 3, wn = wid >> 2;
    const int n0 = blockIdx.x * 128;
    const int m0 = blockIdx.y * 128;
    const int nb = blockIdx.z;
    const int W3 = (Kd >> 2) * 6;
    const float* Bp = B + (size_t)nb*BstrN + n0;
    float*       Cp = C + (size_t)nb*CstrN;

    const int kb2 = (tid >> 5) * 2;
    const int bn4 = (tid & 31) * 4;

    const uint32_t aAddr0 = sBase + (uint32_t)((wm*32 + (lane & 15))*AP + (lane >> 4)*4)*4;

    float acc[2][8][4];
#pragma unroll
    for (int i = 0; i < 2; i++)
#pragma unroll
        for (int j = 0; j < 8; j++)
#pragma unroll
            for (int t = 0; t < 4; t++) acc[i][j][t] = 0.f;

    float4 rB[2][2];

    auto cpA = [&](int it){
        const int buf = it & 1;
#pragma unroll
        for (int j = 0; j < 6; j++) {
            const int ch = tid + j*256;
            const int row = ch / 12, w16 = ch - row*12;
            cpa16(sBase + (uint32_t)(buf*BUFW + row*AP + w16*4)*4,
                  At + (size_t)(m0 + row)*W3 + it*48 + w16*4);
        }
        cpcommit();
    };
    auto ldgB = [&](int it){
        const int k0 = it * 32;
#pragma unroll
        for (int q = 0; q < 2; q++) {
            const int k = k0 + kb2 + q*16;
            rB[q][0] = *(const float4*)(Bp + (size_t)k*HWP + bn4);
            rB[q][1] = *(const float4*)(Bp + (size_t)(k+1)*HWP + bn4);
        }
    };
    auto stsB = [&](int buf){
        uint32_t* bw = sm + buf*BUFW + AWBUF;
#pragma unroll
        for (int q = 0; q < 2; q++)
            storeB2x4(bw, ((tid>>5) + q*8)*3, bn4, (const float*)&rB[q][0], (const float*)&rB[q][1]);
    };

    const int nIter = Kd / 32;
    cpA(0); ldgB(0); stsB(0); cpwait<0>(); __syncthreads();
    for (int it = 0; it < nIter; ++it) {
        const int cur = it & 1;
        if (it + 1 < nIter) { cpA(it + 1); ldgB(it + 1); }
        mma_compute(aAddr0 + cur*BUFW*4, sm + cur*BUFW + AWBUF, acc, wn, lane);
        if (it + 1 < nIter) { stsB(cur ^ 1); cpwait<0>(); __syncthreads(); }
    }

    const int lq = lane >> 2, lr = lane & 3;
#pragma unroll
    for (int mt = 0; mt < 2; mt++) {
        const int r0 = m0 + wm*32 + mt*16 + lq;
        const float bv0 = __ldg(&bias[r0]);
        const float bv1 = __ldg(&bias[r0 + 8]);
#pragma unroll
        for (int nt = 0; nt < 8; nt++) {
            const int cb = n0 + wn*64 + nt*8 + 2*lr;
            float2 v0 = make_float2(acc[mt][nt][0] + bv0, acc[mt][nt][1] + bv0);
            float2 v1 = make_float2(acc[mt][nt][2] + bv1, acc[mt][nt][3] + bv1);
            if (RELU) {
                v0.x = fmaxf(v0.x, 0.f); v0.y = fmaxf(v0.y, 0.f);
                v1.x = fmaxf(v1.x, 0.f); v1.y = fmaxf(v1.y, 0.f);
            }
            *(float2*)(Cp + (size_t)r0*HWP + cb)       = v0;
            *(float2*)(Cp + (size_t)(r0 + 8)*HWP + cb) = v1;
        }
    }
}

// ---------------- conv: halo-tiled implicit GEMM (bf16x3 mma) ----------------
__global__ void __launch_bounds__(256, 2) conv_mma(const float* __restrict__ b_ad)
{
    extern __shared__ uint32_t sm[];
    const uint32_t sBase = su32(sm);
    uint32_t* bw = sm + 2*AWBUF;

    const int tid = threadIdx.x, lane = tid & 31, wid = tid >> 5;
    const int wm = wid & 3, wn = wid >> 2;   // wm: 32-o rows; wn: 48-hw cols
    const int bx = blockIdx.x;               // 24 tiles of 2 rows
    const int h0 = bx*2;
    const int hw0 = bx*96;
    const int nb  = blockIdx.y;
    const float* fb = g_f + (size_t)nb*CM*HWP;
    const uint32_t* dwt = g_dynWT + (size_t)nb*KR*CM*192;

    const uint32_t aAddr0 = sBase + (uint32_t)((wm*32 + (lane & 15))*AP + (lane >> 4)*4)*4;

    // zero the 8 pad columns (w=-1, w=48 per input row) for all 48 k-words
    for (int i = tid; i < 48*8; i += 256) {
        const int row = i >> 3, e = i & 7;
        const int r = e >> 1, side = e & 1;
        bw[row*CPW + r*50 + (side ? 49 : 0)] = 0;
    }

    float acc[2][6][4];
#pragma unroll
    for (int i = 0; i < 2; i++)
#pragma unroll
        for (int j = 0; j < 6; j++)
#pragma unroll
            for (int t = 0; t < 4; t++) acc[i][j][t] = 0.f;

    auto cpA = [&](int it){                 // it = chunk*9 + kk
        const int buf = it & 1;
        const int kk = it % 9, c48 = (it/9)*48;
        const uint32_t* src = dwt + (size_t)kk*CM*192;
#pragma unroll
        for (int j = 0; j < 6; j++) {
            const int ch = tid + j*256;
            const int row = ch / 12, w16 = ch - row*12;
            cpa16(sBase + (uint32_t)(buf*AWBUF + row*AP + w16*4)*4,
                  src + (size_t)row*192 + c48 + w16*4);
        }
        cpcommit();
    };

    auto loadB = [&](int chunk){
        const int c0 = chunk*32;
#pragma unroll
        for (int j = 0; j < 12; j++) {
            const int slot = tid + j*256;        // 0..3071 = 16 pairs x 192 pos
            const int p = slot / 192, pos = slot - p*192;
            const int r = pos / 48, w = pos - r*48;
            const int hin = h0 - 1 + r;
            const bool ok = (hin >= 0) && (hin < HH);
            float v0 = 0.f, v1 = 0.f;
            if (ok) {
                const float* fp = fb + (size_t)(c0 + 2*p)*HWP + hin*WW + w;
                v0 = __ldg(fp);
                v1 = __ldg(fp + HWP);
            }
            uint16_t H0,L0,H1,L1;
            bsplit(v0, H0, L0); bsplit(v1, H1, L1);
            uint32_t* q = bw + (3*p)*CPW + r*50 + 1 + w;
            q[0]     = pk(H0,H0);
            q[CPW]   = pk(L0,H1);
            q[2*CPW] = pk(H1,L1);
        }
    };

    const int lq = lane >> 2, lr = lane & 3;
    const int colb = (wn + 1)*50 + 1 + lq;   // fragment col base (tap 0 center)

    auto mmaStep = [&](int buf, int tapoff){
        const uint32_t aAddr = aAddr0 + (uint32_t)(buf*AWBUF)*4;
#pragma unroll
        for (int s = 0; s < 6; s++) {
            uint32_t a[2][4];
            ldmA(a[0], aAddr + s*32);
            ldmA(a[1], aAddr + 16*AP*4 + s*32);
            const uint32_t* pb0 = bw + (s*8 + lr)*CPW + tapoff;
#pragma unroll
            for (int nt = 0; nt < 6; nt++) {
                const int col = colb + nt*8;
                uint32_t b[2];
                b[0] = pb0[col];
                b[1] = pb0[4*CPW + col];
                mma16(acc[0][nt], a[0], b);
                mma16(acc[1][nt], a[1], b);
            }
        }
    };

    cpA(0); cpwait<0>();
    for (int chunk = 0; chunk < 4; chunk++) {
        __syncthreads();                 // prior readers done / zeros+A visible
        loadB(chunk);
        __syncthreads();
#pragma unroll
        for (int kk = 0; kk < KR; kk++) {
            const int it = chunk*9 + kk;
            if (it + 1 < 36) cpA(it + 1);
            const int kh = kk/3 - 1, kw = kk - (kk/3)*3 - 1;
            mmaStep(it & 1, kh*50 + kw);
            if (it + 1 < 36) { cpwait<0>(); __syncthreads(); }
        }
    }

    // epilogue: y[o][hw0 + wn*48 + nt*8 + 2lr + {0,1}]
    float* yb = g_y + (size_t)nb*CM*HWP;
#pragma unroll
    for (int mt = 0; mt < 2; mt++) {
        const int o0 = wm*32 + mt*16 + lq;
        const float bv0 = __ldg(&b_ad[o0]);
        const float bv1 = __ldg(&b_ad[o0 + 8]);
#pragma unroll
        for (int nt = 0; nt < 6; nt++) {
            const int cb = hw0 + wn*48 + nt*8 + 2*lr;
            float2 v0 = make_float2(acc[mt][nt][0] + bv0, acc[mt][nt][1] + bv0);
            float2 v1 = make_float2(acc[mt][nt][2] + bv1, acc[mt][nt][3] + bv1);
            *(float2*)(yb + (size_t)o0*HWP + cb)       = v0;
            *(float2*)(yb + (size_t)(o0 + 8)*HWP + cb) = v1;
        }
    }
}

// ---------------- launch -----------------------------------------------------
// Dual-stream fork/join: the pool->branch->dynw chain is independent of
// wtrip_Wc->gemm1, so it runs on a side stream and joins before conv.
extern "C" void kernel_launch(void* const* d_in, const int* in_sizes, int n_in,
                              void* d_out, int out_size) {
    const float* x    = (const float*)d_in[0];
    const float* Wc   = (const float*)d_in[1];
    const float* bc   = (const float*)d_in[2];
    const float* Wkk  = (const float*)d_in[3];
    const float* bkk  = (const float*)d_in[4];
    const float* Wck  = (const float*)d_in[5];
    const float* bck  = (const float*)d_in[6];
    const float* b_ad = (const float*)d_in[7];
    const float* Wf   = (const float*)d_in[8];
    const float* bf   = (const float*)d_in[9];
    float* out = (float*)d_out;

    float* df; float* dy;
    uint32_t* dWcT; uint32_t* dWfT;
    cudaGetSymbolAddress((void**)&df,   g_f);
    cudaGetSymbolAddress((void**)&dy,   g_y);
    cudaGetSymbolAddress((void**)&dWcT, g_WcT);
    cudaGetSymbolAddress((void**)&dWfT, g_WfT);

    cudaFuncSetAttribute(gemm_mma<true>,  cudaFuncAttributeMaxDynamicSharedMemorySize, SMEM_BYTES);
    cudaFuncSetAttribute(gemm_mma<false>, cudaFuncAttributeMaxDynamicSharedMemorySize, SMEM_BYTES);
    cudaFuncSetAttribute(conv_mma,        cudaFuncAttributeMaxDynamicSharedMemorySize, CONV_SMEM);

    // Side stream + fork/join events. kernel_launch is only invoked a handful
    // of times (correctness + capture); replays execute the captured graph, so
    // these creations do not accumulate meaningfully.
    cudaStream_t s2;
    cudaStreamCreateWithFlags(&s2, cudaStreamNonBlocking);
    cudaEvent_t evFork, evJoin;
    cudaEventCreateWithFlags(&evFork, cudaEventDisableTiming);
    cudaEventCreateWithFlags(&evJoin, cudaEventDisableTiming);

    // fork: side chain pool -> branch -> dynw on s2
    cudaEventRecord(evFork, 0);
    cudaStreamWaitEvent(s2, evFork, 0);
    pool_kernel<<<dim3(CC/16, NN), 256, 0, s2>>>(x);
    branch_kernel<<<dim3(8, NN), 256, 0, s2>>>(Wc, bc);
    dynw_kernel<<<dim3(KR, NN), 256, 0, s2>>>(Wkk, bkk, Wck, bck);
    cudaEventRecord(evJoin, s2);

    // main stream: weight encodes + gemm1 (independent of the side chain)
    wtrip_kernel<<<CM*(CC/4)/256, 256>>>(Wc, dWcT, CC);
    wtrip_kernel<<<PP*(CM/4)/256, 256>>>(Wf, dWfT, CM);
    gemm_mma<true><<<dim3(HWP/128, 1, NN), 256, SMEM_BYTES>>>(
        dWcT, x, df, bc, CC, (size_t)CC*HWP, (size_t)CM*HWP);

    // join: conv needs gemm1 (f) + dynw (dynWT)
    cudaStreamWaitEvent(0, evJoin, 0);
    conv_mma<<<dim3(24, NN), 256, CONV_SMEM>>>(b_ad);

    // out = Wf @ y + bf
    gemm_mma<false><<<dim3(HWP/128, PP/128, NN), 256, SMEM_BYTES>>>(
        dWfT, dy, out, bf, CM, (size_t)CM*HWP, (size_t)PP*HWP);
}